// round 13
// baseline (speedup 1.0000x reference)
#include <cuda_runtime.h>
#include <cuda_fp16.h>
#include <cstdint>

#define B_    2
#define N_    1024
#define DM    640
#define SH    5
#define DH    128
#define NH    14
#define KC    32
#define VW    (NH * DH)       // 1792
#define QKVW  3072
#define KOFF  640
#define VOFF  1280
#define KE_P  (2 * DM)        // 1280  [xh|xl] / [yh|yh]
#define KE_C  (2 * VW)        // 3584
#define ZSPLIT 4

// -------- device scratch --------
__device__ float g_qkv [B_ * N_ * QKVW];
__device__ float g_part[ZSPLIT * B_ * N_ * DM];

__device__ __half gb_q [B_ * N_ * KE_P];
__device__ __half gb_k [B_ * N_ * KE_P];
__device__ __half gb_v [B_ * N_ * KE_P];
__device__ __half gb_w [QKVW * KE_P];
__device__ __half gb_Ck[DM * KE_C];
__device__ __half gb_at[B_ * N_ * KE_C];

__constant__ int c_dil  [SH] = {1, 1, 2, 4, 8};
__constant__ int c_sub  [NH] = {0,0,0,0,0, 1,1,1,1,1, 2,2, 3, 4};
__constant__ int c_dilh [NH] = {1,1,1,1,1, 1,1,1,1,1, 2,2, 4, 8};

// ============================ helpers ======================================
__device__ __forceinline__ uint32_t smem_u32(const void* p) {
    return (uint32_t)__cvta_generic_to_shared(p);
}
__device__ __forceinline__ void cp_async16(uint32_t saddr, const void* g) {
    asm volatile("cp.async.cg.shared.global [%0], [%1], 16;"
                 :: "r"(saddr), "l"(g) : "memory");
}
#define CP_COMMIT() asm volatile("cp.async.commit_group;" ::: "memory")
#define CP_WAIT1()  asm volatile("cp.async.wait_group 1;"  ::: "memory")

__device__ __forceinline__ void ldmx4(uint32_t* r, uint32_t a) {
    asm volatile("ldmatrix.sync.aligned.m8n8.x4.shared.b16 {%0,%1,%2,%3}, [%4];"
        : "=r"(r[0]), "=r"(r[1]), "=r"(r[2]), "=r"(r[3]) : "r"(a));
}
__device__ __forceinline__ void mma16816(float* d, const uint32_t* a,
                                         const uint32_t b0, const uint32_t b1) {
    asm volatile(
        "mma.sync.aligned.m16n8k16.row.col.f32.f16.f16.f32 "
        "{%0,%1,%2,%3}, {%4,%5,%6,%7}, {%8,%9}, {%0,%1,%2,%3};"
        : "+f"(d[0]), "+f"(d[1]), "+f"(d[2]), "+f"(d[3])
        : "r"(a[0]), "r"(a[1]), "r"(a[2]), "r"(a[3]), "r"(b0), "r"(b1));
}

// ---------------------------------------------------------------------------
// HMMA fp16 GEMM over pre-split operands (R11 exact).
// 128x128 CTA tile, 128 threads (4 warps, 64x64 warp tile), BK=32,
// 3-stage cp.async pipeline. 61.4 KB smem -> 3 CTAs/SM.
// ---------------------------------------------------------------------------
#define BKT   32
#define LDS_  40                 // 32 + 8 pad (fp16 elems)
#define TSZ   (128 * LDS_ * 2)   // 10240 B per tile
#define STAGE (2 * TSZ)          // 20480 B (A + B)
#define SMEM_GEMM (3 * STAGE)    // 61440 B

__device__ __forceinline__ void hmma_gemm_body(
    const __half* __restrict__ A, const __half* __restrict__ W,
    const float* __restrict__ bias_tile, float* __restrict__ C,
    int nk, int lda, int ldw, int ldc)
{
    extern __shared__ char smem[];
    const uint32_t smb = smem_u32(smem);

    const int bm = blockIdx.y * 128;
    const int bn = blockIdx.x * 128;
    const int tid = threadIdx.x;                 // 0..127
    const int lane = tid & 31, wid = tid >> 5;   // 4 warps
    const int wm = (wid & 1) * 64;
    const int wn = (wid >> 1) * 64;

    float acc[4][8][4] = {};

    auto issue = [&](int it2) {
        if (it2 < nk) {
            const uint32_t st = smb + (it2 % 3) * STAGE;
            const int cb = it2 * BKT;
#pragma unroll
            for (int i = 0; i < 4; i++) {
                const int idx = tid + i * 128;
                const int row = idx >> 2;           // 0..127
                const int col = (idx & 3) * 8;      // 0,8,16,24
                const uint32_t so = (uint32_t)(row * LDS_ + col) * 2;
                cp_async16(st +       so, A + (size_t)(bm + row) * lda + cb + col);
                cp_async16(st + TSZ + so, W + (size_t)(bn + row) * ldw + cb + col);
            }
        }
        CP_COMMIT();
    };

    issue(0);
    issue(1);

    const int a_row = wm + (lane & 15);
    const int a_kof = (lane >> 4) * 8;
    const int b_row = wn + (lane & 7) + (lane >> 4) * 8;
    const int b_kof = ((lane >> 3) & 1) * 8;

    for (int it = 0; it < nk; ++it) {
        CP_WAIT1();
        __syncthreads();
        issue(it + 2);

        const uint32_t st = smb + (it % 3) * STAGE;
        const uint32_t sA = st;
        const uint32_t sB = st + TSZ;
#pragma unroll
        for (int ks = 0; ks < 2; ++ks) {
            const int k0 = ks * 16;
            uint32_t af[4][4], bf[4][4];
#pragma unroll
            for (int mi = 0; mi < 4; mi++)
                ldmx4(af[mi], sA + (uint32_t)((a_row + mi * 16) * LDS_ + k0 + a_kof) * 2);
#pragma unroll
            for (int g2 = 0; g2 < 4; g2++)
                ldmx4(bf[g2], sB + (uint32_t)((b_row + g2 * 16) * LDS_ + k0 + b_kof) * 2);
#pragma unroll
            for (int mi = 0; mi < 4; mi++)
#pragma unroll
                for (int ni = 0; ni < 8; ni++)
                    mma16816(acc[mi][ni], af[mi],
                             bf[ni >> 1][(ni & 1) * 2], bf[ni >> 1][(ni & 1) * 2 + 1]);
        }
    }

    const int g = lane >> 2, t = lane & 3;
#pragma unroll
    for (int mi = 0; mi < 4; mi++) {
        const int row0 = bm + wm + mi * 16 + g;
#pragma unroll
        for (int ni = 0; ni < 8; ni++) {
            const int colL = wn + ni * 8 + t * 2;
            float b0 = 0.f, b1 = 0.f;
            if (bias_tile) { b0 = bias_tile[colL]; b1 = bias_tile[colL + 1]; }
            float2 v0 = {acc[mi][ni][0] + b0, acc[mi][ni][1] + b1};
            float2 v1 = {acc[mi][ni][2] + b0, acc[mi][ni][3] + b1};
            *reinterpret_cast<float2*>(&C[(size_t)row0 * ldc + bn + colL]) = v0;
            *reinterpret_cast<float2*>(&C[(size_t)(row0 + 8) * ldc + bn + colL]) = v1;
        }
    }
}

__global__ __launch_bounds__(128, 3) void hmma_qkv_kernel(
    const float* __restrict__ Qb, const float* __restrict__ Kb,
    const float* __restrict__ Vb)
{
    const int bn = blockIdx.x * 128;
    const __half* A = (bn < KOFF) ? gb_q : (bn < VOFF) ? gb_k : gb_v;
    const float* bias = (bn < KOFF) ? (Qb + bn)
                      : (bn < VOFF) ? (Kb + bn - KOFF)
                                    : (Vb + bn - VOFF);
    hmma_gemm_body(A, gb_w, bias, g_qkv, KE_P / BKT, KE_P, KE_P, QKVW);
}

__global__ __launch_bounds__(128, 3) void hmma_col_kernel()
{
    const int z = blockIdx.z;            // 112 chunks of 32: 28 per z? no: KE_C/BKT=112, 28 per z
    const int cstart = z * (KE_C / BKT / ZSPLIT);
    hmma_gemm_body(gb_at + cstart * BKT, gb_Ck + cstart * BKT, nullptr,
                   g_part + (size_t)z * (B_ * N_ * DM),
                   KE_C / BKT / ZSPLIT, KE_C, KE_C, DM);
}

// ---------------------------------------------------------------------------
// fp32 -> fp16 split conversions, row layout stride 2K.
//   activations: [xh (K) | xl (K)]      weights: [yh (K) | yh (K)]
// ---------------------------------------------------------------------------
__device__ __forceinline__ void cvt_act(
    const float* __restrict__ inrow, __half* __restrict__ outrow, int k, int K)
{
    const float2 x = reinterpret_cast<const float2*>(inrow)[k];
    const __half h0 = __float2half_rn(x.x);
    const __half h1 = __float2half_rn(x.y);
    const __half l0 = __float2half_rn(x.x - __half2float(h0));
    const __half l1 = __float2half_rn(x.y - __half2float(h1));
    __half2 hh; hh.x = h0; hh.y = h1;
    __half2 ll; ll.x = l0; ll.y = l1;
    __half2* orow = reinterpret_cast<__half2*>(outrow);
    orow[k] = hh;
    orow[(K >> 1) + k] = ll;
}
__device__ __forceinline__ void cvt_wt(
    const float* __restrict__ inrow, __half* __restrict__ outrow, int k, int K)
{
    const float2 x = reinterpret_cast<const float2*>(inrow)[k];
    __half2 hh; hh.x = __float2half_rn(x.x); hh.y = __float2half_rn(x.y);
    __half2* orow = reinterpret_cast<__half2*>(outrow);
    orow[k] = hh;
    orow[(K >> 1) + k] = hh;     // duplicate hi
}

__global__ __launch_bounds__(256) void cvt_qkv_kernel(
    const float* __restrict__ q, const float* __restrict__ k,
    const float* __restrict__ v)
{
    const int i = blockIdx.x * 256 + threadIdx.x;
    if (i >= B_ * N_ * DM / 2) return;
    const int which = blockIdx.y;
    const float* in = (which == 0) ? q : (which == 1) ? k : v;
    __half* out = (which == 0) ? gb_q : (which == 1) ? gb_k : gb_v;
    const int r = i / (DM / 2), kk = i % (DM / 2);
    cvt_act(in + (size_t)r * DM, out + (size_t)r * KE_P, kk, DM);
}

// merged weight conversion: proj weights (Qk|Kk|Vk) then Ck, one launch
#define WPAIRS (QKVW * DM / 2)
#define CPAIRS (DM * VW / 2)
__global__ __launch_bounds__(256) void cvt_wts_kernel(
    const float* __restrict__ Qk, const float* __restrict__ Kk,
    const float* __restrict__ Vk, const float* __restrict__ Ck)
{
    const int i = blockIdx.x * 256 + threadIdx.x;
    if (i < WPAIRS) {
        const int r = i / (DM / 2), kk = i % (DM / 2);
        const float* src = (r < KOFF) ? (Qk + (size_t)r * DM)
                         : (r < VOFF) ? (Kk + (size_t)(r - KOFF) * DM)
                                      : (Vk + (size_t)(r - VOFF) * DM);
        cvt_wt(src, gb_w + (size_t)r * KE_P, kk, DM);
    } else if (i < WPAIRS + CPAIRS) {
        const int j = i - WPAIRS;
        const int r = j / (VW / 2), kk = j % (VW / 2);
        cvt_wt(Ck + (size_t)r * VW, gb_Ck + (size_t)r * KE_C, kk, VW);
    }
}

__global__ __launch_bounds__(256) void add_bias_kernel(
    const float* __restrict__ Cb, float* __restrict__ out)
{
    const int i = blockIdx.x * 256 + threadIdx.x;
    const float4 p0 = reinterpret_cast<const float4*>(g_part)[i];
    const float4 p1 = reinterpret_cast<const float4*>(g_part + (size_t)B_ * N_ * DM)[i];
    const float4 p2 = reinterpret_cast<const float4*>(g_part + (size_t)2 * B_ * N_ * DM)[i];
    const float4 p3 = reinterpret_cast<const float4*>(g_part + (size_t)3 * B_ * N_ * DM)[i];
    const float4 bb = reinterpret_cast<const float4*>(Cb)[i % (DM / 4)];
    float4 o = {p0.x + p1.x + p2.x + p3.x + bb.x,
                p0.y + p1.y + p2.y + p3.y + bb.y,
                p0.z + p1.z + p2.z + p3.z + bb.z,
                p0.w + p1.w + p2.w + p3.w + bb.w};
    reinterpret_cast<float4*>(out)[i] = o;
}

// ---------------------------------------------------------------------------
// Fused banded attention — ONE CTA PER (tile z, head h, batch b).
// Scores recomputed per head (cheap); no serial head loop.
// ---------------------------------------------------------------------------
__global__ __launch_bounds__(256) void attn_fused_kernel(
    const float* __restrict__ Kb, const float* __restrict__ Vb,
    const float* __restrict__ Sk, const float* __restrict__ Sb)
{
    const int z   = blockIdx.x;
    const int h   = blockIdx.y;
    const int b   = blockIdx.z;
    const int tid = threadIdx.x;
    const int lane = tid & 31;
    const int wrp  = tid >> 5;

    const int s   = c_sub[h];
    const int dil = c_dilh[h];
    const int pl  = ((KC - 1) * dil) >> 1;
    const int cpr = 32 / dil;
    const int r0  = z / cpr;
    const int c0  = z % cpr;
    const int n0  = r0 + c0 * 32 * dil;
    const int base = n0 - pl;

    __shared__ float kv [63][DH];
    __shared__ float ssc[32][33];
    __shared__ float sks[32][32];
    __shared__ float shs[32][33];

    // ---- load K band tile for subhead s ----
    for (int i = tid; i < 63 * DH; i += 256) {
        const int u = i >> 7, col = i & 127;
        const int idx = base + u * dil;
        kv[u][col] = (idx >= 0 && idx < N_)
            ? g_qkv[(size_t)(b * N_ + idx) * QKVW + KOFF + s * DH + col]
            : Kb[s * DH + col];
    }
    // ---- load Sk[h] (no dependence on kv; before first sync) ----
    for (int i = tid; i < KC * KC; i += 256)
        sks[i >> 5][i & 31] = Sk[(size_t)h * KC * KC + i];
    __syncthreads();

    // ---- scores: warp w handles t = w, w+8, w+16, w+24 ----
#pragma unroll
    for (int ti = 0; ti < 4; ti++) {
        const int t  = wrp + ti * 8;
        const int nt = n0 + t * dil;
        const float4 ql = *reinterpret_cast<const float4*>(
            g_qkv + (size_t)(b * N_ + nt) * QKVW + s * DH + lane * 4);
#pragma unroll
        for (int k = 0; k < KC; k++) {
            const float4 kf = *reinterpret_cast<const float4*>(&kv[t + k][lane * 4]);
            float p = ql.x*kf.x + ql.y*kf.y + ql.z*kf.z + ql.w*kf.w;
            p += __shfl_xor_sync(0xffffffffu, p, 16);
            p += __shfl_xor_sync(0xffffffffu, p, 8);
            p += __shfl_xor_sync(0xffffffffu, p, 4);
            p += __shfl_xor_sync(0xffffffffu, p, 2);
            p += __shfl_xor_sync(0xffffffffu, p, 1);
            if (lane == 0) ssc[t][k] = p;
        }
    }
    __syncthreads();

    // ---- Pos_Sampling: shs[t][j] = Sb[h,j] + sum_k ssc[t][k]*sks[j][k] ----
    for (int i = tid; i < 32 * KC; i += 256) {
        const int t = i & 31, j = i >> 5;
        float acc = Sb[h * KC + j];
#pragma unroll
        for (int k = 0; k < KC; k++) acc += ssc[t][k] * sks[j][k];
        shs[t][j] = acc;
    }
    __syncthreads();

    // ---- softmax + overlap V tile load ----
    if (tid < 32) {
        float* rowp = shs[tid];
        float m = rowp[0];
#pragma unroll
        for (int j = 1; j < KC; j++) m = fmaxf(m, rowp[j]);
        float sum = 0.0f;
#pragma unroll
        for (int j = 0; j < KC; j++) { float e = expf(rowp[j]-m); rowp[j] = e; sum += e; }
        const float inv = 1.0f / sum;
#pragma unroll
        for (int j = 0; j < KC; j++) rowp[j] *= inv;
    }
    __syncthreads();

    // ---- load V band tile for head h (reuse kv) ----
    for (int i = tid; i < 63 * DH; i += 256) {
        const int u = i >> 7, col = i & 127;
        const int idx = base + u * dil;
        kv[u][col] = (idx >= 0 && idx < N_)
            ? g_qkv[(size_t)(b * N_ + idx) * QKVW + VOFF + h * DH + col]
            : Vb[h * DH + col];
    }
    __syncthreads();

    // ---- apply + write fp16 [h|l] to gb_at ----
    const int dq = lane * 4;
#pragma unroll
    for (int tt = 0; tt < 4; tt++) {
        const int t  = wrp + tt * 8;
        const int nt = n0 + t * dil;
        float4 acc = {0.f, 0.f, 0.f, 0.f};
#pragma unroll
        for (int j = 0; j < KC; j++) {
            const float wv = shs[t][j];
            const float4 v = *reinterpret_cast<const float4*>(&kv[t + j][dq]);
            acc.x += wv * v.x; acc.y += wv * v.y;
            acc.z += wv * v.z; acc.w += wv * v.w;
        }
        const __half h0 = __float2half_rn(acc.x);
        const __half h1 = __float2half_rn(acc.y);
        const __half h2 = __float2half_rn(acc.z);
        const __half h3 = __float2half_rn(acc.w);
        const __half l0 = __float2half_rn(acc.x - __half2float(h0));
        const __half l1 = __float2half_rn(acc.y - __half2float(h1));
        const __half l2 = __float2half_rn(acc.z - __half2float(h2));
        const __half l3 = __float2half_rn(acc.w - __half2float(h3));
        __half2 hp0; hp0.x = h0; hp0.y = h1;
        __half2 hp1; hp1.x = h2; hp1.y = h3;
        __half2 lp0; lp0.x = l0; lp0.y = l1;
        __half2 lp1; lp1.x = l2; lp1.y = l3;
        uint2 hv, lv;
        hv.x = *reinterpret_cast<uint32_t*>(&hp0);
        hv.y = *reinterpret_cast<uint32_t*>(&hp1);
        lv.x = *reinterpret_cast<uint32_t*>(&lp0);
        lv.y = *reinterpret_cast<uint32_t*>(&lp1);
        __half* orow = gb_at + (size_t)(b * N_ + nt) * KE_C;
        const int col = h * DH + dq;
        *reinterpret_cast<uint2*>(orow + col)      = hv;
        *reinterpret_cast<uint2*>(orow + VW + col) = lv;
    }
}

extern "C" void kernel_launch(void* const* d_in, const int* in_sizes, int n_in,
                              void* d_out, int out_size)
{
    const float* query = (const float*)d_in[0];
    const float* key   = (const float*)d_in[1];
    const float* value = (const float*)d_in[2];
    const float* Qk    = (const float*)d_in[3];
    const float* Qb    = (const float*)d_in[4];
    const float* Kk    = (const float*)d_in[5];
    const float* Kb    = (const float*)d_in[6];
    const float* Vk    = (const float*)d_in[7];
    const float* Vb    = (const float*)d_in[8];
    const float* Sk    = (const float*)d_in[9];
    const float* Sb    = (const float*)d_in[10];
    const float* Ck    = (const float*)d_in[11];
    const float* Cb    = (const float*)d_in[12];
    float* out = (float*)d_out;

    cudaFuncSetAttribute(hmma_qkv_kernel,
        cudaFuncAttributeMaxDynamicSharedMemorySize, SMEM_GEMM);
    cudaFuncSetAttribute(hmma_col_kernel,
        cudaFuncAttributeMaxDynamicSharedMemorySize, SMEM_GEMM);

    const int M = B_ * N_;  // 2048

    {   // activations q/k/v [xh|xl] in one launch
        const int pairs = M * DM / 2;
        dim3 grid((pairs + 255) / 256, 3);
        cvt_qkv_kernel<<<grid, 256>>>(query, key, value);
    }
    {   // merged weight conversions (Qk|Kk|Vk then Ck), one launch
        const int pairs = WPAIRS + CPAIRS;
        cvt_wts_kernel<<<(pairs + 255) / 256, 256>>>(Qk, Kk, Vk, Ck);
    }
    {   // fused Q|K|V projection: grid (24, 16) = 384 CTAs, 3 CTAs/SM
        dim3 grid(QKVW / 128, M / 128);
        hmma_qkv_kernel<<<grid, 128, SMEM_GEMM>>>(Qb, Kb, Vb);
    }
    {   // fused banded attention: one CTA per (tile, head, batch)
        dim3 grid(32, NH, B_);
        attn_fused_kernel<<<grid, 256>>>(Kb, Vb, Sk, Sb);
    }
    {   // collapse split-K=4: grid (5, 16, 4) = 320 CTAs
        dim3 grid(DM / 128, M / 128, ZSPLIT);
        hmma_col_kernel<<<grid, 128, SMEM_GEMM>>>();
    }
    add_bias_kernel<<<(M * DM / 4) / 256, 256>>>(Cb, out);
}

// round 14
// speedup vs baseline: 1.0595x; 1.0595x over previous
#include <cuda_runtime.h>
#include <cuda_fp16.h>
#include <cstdint>

#define B_    2
#define N_    1024
#define DM    640
#define SH    5
#define DH    128
#define NH    14
#define KC    32
#define VW    (NH * DH)       // 1792
#define QKVW  3072
#define KOFF  640
#define VOFF  1280
#define KE_P  (2 * DM)        // 1280  [xh|xl] / [yh|yh]
#define KE_C  (2 * VW)        // 3584
#define ZSPLIT 4

// -------- device scratch --------
__device__ float g_qkv [B_ * N_ * QKVW];

__device__ __half gb_q [B_ * N_ * KE_P];
__device__ __half gb_k [B_ * N_ * KE_P];
__device__ __half gb_v [B_ * N_ * KE_P];
__device__ __half gb_w [QKVW * KE_P];
__device__ __half gb_Ck[DM * KE_C];
__device__ __half gb_at[B_ * N_ * KE_C];

__constant__ int c_dil  [SH] = {1, 1, 2, 4, 8};
__constant__ int c_hbase[SH] = {0, 5, 10, 12, 13};
__constant__ int c_hcnt [SH] = {5, 5, 2, 1, 1};

// ============================ helpers ======================================
__device__ __forceinline__ uint32_t smem_u32(const void* p) {
    return (uint32_t)__cvta_generic_to_shared(p);
}
__device__ __forceinline__ void cp_async16(uint32_t saddr, const void* g) {
    asm volatile("cp.async.cg.shared.global [%0], [%1], 16;"
                 :: "r"(saddr), "l"(g) : "memory");
}
#define CP_COMMIT() asm volatile("cp.async.commit_group;" ::: "memory")
#define CP_WAIT1()  asm volatile("cp.async.wait_group 1;"  ::: "memory")

__device__ __forceinline__ void ldmx4(uint32_t* r, uint32_t a) {
    asm volatile("ldmatrix.sync.aligned.m8n8.x4.shared.b16 {%0,%1,%2,%3}, [%4];"
        : "=r"(r[0]), "=r"(r[1]), "=r"(r[2]), "=r"(r[3]) : "r"(a));
}
__device__ __forceinline__ void mma16816(float* d, const uint32_t* a,
                                         const uint32_t b0, const uint32_t b1) {
    asm volatile(
        "mma.sync.aligned.m16n8k16.row.col.f32.f16.f16.f32 "
        "{%0,%1,%2,%3}, {%4,%5,%6,%7}, {%8,%9}, {%0,%1,%2,%3};"
        : "+f"(d[0]), "+f"(d[1]), "+f"(d[2]), "+f"(d[3])
        : "r"(a[0]), "r"(a[1]), "r"(a[2]), "r"(a[3]), "r"(b0), "r"(b1));
}

// ---------------------------------------------------------------------------
// HMMA fp16 GEMM over pre-split operands (R11 exact mainloop).
// 128x128 CTA tile, 128 threads (4 warps, 64x64 warp tile), BK=32,
// 3-stage cp.async pipeline. 61.4 KB smem -> 3 CTAs/SM.
// atomic_out=0: store with bias; atomic_out=1: atomicAdd into C.
// ---------------------------------------------------------------------------
#define BKT   32
#define LDS_  40                 // 32 + 8 pad (fp16 elems)
#define TSZ   (128 * LDS_ * 2)   // 10240 B per tile
#define STAGE (2 * TSZ)          // 20480 B (A + B)
#define SMEM_GEMM (3 * STAGE)    // 61440 B

__device__ __forceinline__ void hmma_gemm_body(
    const __half* __restrict__ A, const __half* __restrict__ W,
    const float* __restrict__ bias_tile, float* __restrict__ C,
    int nk, int lda, int ldw, int ldc, int atomic_out)
{
    extern __shared__ char smem[];
    const uint32_t smb = smem_u32(smem);

    const int bm = blockIdx.y * 128;
    const int bn = blockIdx.x * 128;
    const int tid = threadIdx.x;                 // 0..127
    const int lane = tid & 31, wid = tid >> 5;   // 4 warps
    const int wm = (wid & 1) * 64;
    const int wn = (wid >> 1) * 64;

    float acc[4][8][4] = {};

    auto issue = [&](int it2) {
        if (it2 < nk) {
            const uint32_t st = smb + (it2 % 3) * STAGE;
            const int cb = it2 * BKT;
#pragma unroll
            for (int i = 0; i < 4; i++) {
                const int idx = tid + i * 128;
                const int row = idx >> 2;           // 0..127
                const int col = (idx & 3) * 8;      // 0,8,16,24
                const uint32_t so = (uint32_t)(row * LDS_ + col) * 2;
                cp_async16(st +       so, A + (size_t)(bm + row) * lda + cb + col);
                cp_async16(st + TSZ + so, W + (size_t)(bn + row) * ldw + cb + col);
            }
        }
        CP_COMMIT();
    };

    issue(0);
    issue(1);

    const int a_row = wm + (lane & 15);
    const int a_kof = (lane >> 4) * 8;
    const int b_row = wn + (lane & 7) + (lane >> 4) * 8;
    const int b_kof = ((lane >> 3) & 1) * 8;

    for (int it = 0; it < nk; ++it) {
        CP_WAIT1();
        __syncthreads();
        issue(it + 2);

        const uint32_t st = smb + (it % 3) * STAGE;
        const uint32_t sA = st;
        const uint32_t sB = st + TSZ;
#pragma unroll
        for (int ks = 0; ks < 2; ++ks) {
            const int k0 = ks * 16;
            uint32_t af[4][4], bf[4][4];
#pragma unroll
            for (int mi = 0; mi < 4; mi++)
                ldmx4(af[mi], sA + (uint32_t)((a_row + mi * 16) * LDS_ + k0 + a_kof) * 2);
#pragma unroll
            for (int g2 = 0; g2 < 4; g2++)
                ldmx4(bf[g2], sB + (uint32_t)((b_row + g2 * 16) * LDS_ + k0 + b_kof) * 2);
#pragma unroll
            for (int mi = 0; mi < 4; mi++)
#pragma unroll
                for (int ni = 0; ni < 8; ni++)
                    mma16816(acc[mi][ni], af[mi],
                             bf[ni >> 1][(ni & 1) * 2], bf[ni >> 1][(ni & 1) * 2 + 1]);
        }
    }

    const int g = lane >> 2, t = lane & 3;
#pragma unroll
    for (int mi = 0; mi < 4; mi++) {
        const int row0 = bm + wm + mi * 16 + g;
#pragma unroll
        for (int ni = 0; ni < 8; ni++) {
            const int colL = wn + ni * 8 + t * 2;
            if (atomic_out) {
                float* c0 = &C[(size_t)row0 * ldc + bn + colL];
                float* c1 = &C[(size_t)(row0 + 8) * ldc + bn + colL];
                atomicAdd(c0,     acc[mi][ni][0]);
                atomicAdd(c0 + 1, acc[mi][ni][1]);
                atomicAdd(c1,     acc[mi][ni][2]);
                atomicAdd(c1 + 1, acc[mi][ni][3]);
            } else {
                float b0 = 0.f, b1 = 0.f;
                if (bias_tile) { b0 = bias_tile[colL]; b1 = bias_tile[colL + 1]; }
                float2 v0 = {acc[mi][ni][0] + b0, acc[mi][ni][1] + b1};
                float2 v1 = {acc[mi][ni][2] + b0, acc[mi][ni][3] + b1};
                *reinterpret_cast<float2*>(&C[(size_t)row0 * ldc + bn + colL]) = v0;
                *reinterpret_cast<float2*>(&C[(size_t)(row0 + 8) * ldc + bn + colL]) = v1;
            }
        }
    }
}

__global__ __launch_bounds__(128, 3) void hmma_qkv_kernel(
    const float* __restrict__ Qb, const float* __restrict__ Kb,
    const float* __restrict__ Vb)
{
    const int bn = blockIdx.x * 128;
    const __half* A = (bn < KOFF) ? gb_q : (bn < VOFF) ? gb_k : gb_v;
    const float* bias = (bn < KOFF) ? (Qb + bn)
                      : (bn < VOFF) ? (Kb + bn - KOFF)
                                    : (Vb + bn - VOFF);
    hmma_gemm_body(A, gb_w, bias, g_qkv, KE_P / BKT, KE_P, KE_P, QKVW, 0);
}

__global__ __launch_bounds__(128, 3) void hmma_col_kernel(float* __restrict__ out)
{
    const int z = blockIdx.z;            // 112 chunks of 32: 28 per z
    const int cstart = z * (KE_C / BKT / ZSPLIT);
    hmma_gemm_body(gb_at + cstart * BKT, gb_Ck + cstart * BKT, nullptr,
                   out, KE_C / BKT / ZSPLIT, KE_C, KE_C, DM, 1);
}

// out[i] = Cb[i % DM]  (bias pre-init; collapse atomically accumulates)
__global__ __launch_bounds__(256) void init_out_kernel(
    const float* __restrict__ Cb, float* __restrict__ out)
{
    const int i = blockIdx.x * 256 + threadIdx.x;   // float4 index
    reinterpret_cast<float4*>(out)[i] =
        reinterpret_cast<const float4*>(Cb)[i % (DM / 4)];
}

// ---------------------------------------------------------------------------
// fp32 -> fp16 split conversions, row layout stride 2K.
// ---------------------------------------------------------------------------
__device__ __forceinline__ void cvt_act(
    const float* __restrict__ inrow, __half* __restrict__ outrow, int k, int K)
{
    const float2 x = reinterpret_cast<const float2*>(inrow)[k];
    const __half h0 = __float2half_rn(x.x);
    const __half h1 = __float2half_rn(x.y);
    const __half l0 = __float2half_rn(x.x - __half2float(h0));
    const __half l1 = __float2half_rn(x.y - __half2float(h1));
    __half2 hh; hh.x = h0; hh.y = h1;
    __half2 ll; ll.x = l0; ll.y = l1;
    __half2* orow = reinterpret_cast<__half2*>(outrow);
    orow[k] = hh;
    orow[(K >> 1) + k] = ll;
}
__device__ __forceinline__ void cvt_wt(
    const float* __restrict__ inrow, __half* __restrict__ outrow, int k, int K)
{
    const float2 x = reinterpret_cast<const float2*>(inrow)[k];
    __half2 hh; hh.x = __float2half_rn(x.x); hh.y = __float2half_rn(x.y);
    __half2* orow = reinterpret_cast<__half2*>(outrow);
    orow[k] = hh;
    orow[(K >> 1) + k] = hh;     // duplicate hi
}

__global__ __launch_bounds__(256) void cvt_qkv_kernel(
    const float* __restrict__ q, const float* __restrict__ k,
    const float* __restrict__ v)
{
    const int i = blockIdx.x * 256 + threadIdx.x;
    if (i >= B_ * N_ * DM / 2) return;
    const int which = blockIdx.y;
    const float* in = (which == 0) ? q : (which == 1) ? k : v;
    __half* out = (which == 0) ? gb_q : (which == 1) ? gb_k : gb_v;
    const int r = i / (DM / 2), kk = i % (DM / 2);
    cvt_act(in + (size_t)r * DM, out + (size_t)r * KE_P, kk, DM);
}

#define WPAIRS (QKVW * DM / 2)
#define CPAIRS (DM * VW / 2)
__global__ __launch_bounds__(256) void cvt_wts_kernel(
    const float* __restrict__ Qk, const float* __restrict__ Kk,
    const float* __restrict__ Vk, const float* __restrict__ Ck)
{
    const int i = blockIdx.x * 256 + threadIdx.x;
    if (i < WPAIRS) {
        const int r = i / (DM / 2), kk = i % (DM / 2);
        const float* src = (r < KOFF) ? (Qk + (size_t)r * DM)
                         : (r < VOFF) ? (Kk + (size_t)(r - KOFF) * DM)
                                      : (Vk + (size_t)(r - VOFF) * DM);
        cvt_wt(src, gb_w + (size_t)r * KE_P, kk, DM);
    } else if (i < WPAIRS + CPAIRS) {
        const int j = i - WPAIRS;
        const int r = j / (VW / 2), kk = j % (VW / 2);
        cvt_wt(Ck + (size_t)r * VW, gb_Ck + (size_t)r * KE_C, kk, VW);
    }
}

// ---------------------------------------------------------------------------
// Fused banded attention (R11 exact): grid (32, SH, B), per-subhead head loop.
// Epilogue writes fp16 [h|l] directly to gb_at.
// ---------------------------------------------------------------------------
__global__ __launch_bounds__(256) void attn_fused_kernel(
    const float* __restrict__ Kb, const float* __restrict__ Vb,
    const float* __restrict__ Sk, const float* __restrict__ Sb)
{
    const int z   = blockIdx.x;
    const int s   = blockIdx.y;
    const int b   = blockIdx.z;
    const int tid = threadIdx.x;
    const int lane = tid & 31;
    const int wrp  = tid >> 5;

    const int dil = c_dil[s];
    const int pl  = ((KC - 1) * dil) >> 1;
    const int cpr = 32 / dil;
    const int r0  = z / cpr;
    const int c0  = z % cpr;
    const int n0  = r0 + c0 * 32 * dil;
    const int base = n0 - pl;

    __shared__ float kv [63][DH];
    __shared__ float ssc[32][33];
    __shared__ float sks[32][32];
    __shared__ float shs[32][33];

    for (int i = tid; i < 63 * DH; i += 256) {
        const int u = i >> 7, col = i & 127;
        const int idx = base + u * dil;
        kv[u][col] = (idx >= 0 && idx < N_)
            ? g_qkv[(size_t)(b * N_ + idx) * QKVW + KOFF + s * DH + col]
            : Kb[s * DH + col];
    }
    __syncthreads();

#pragma unroll
    for (int ti = 0; ti < 4; ti++) {
        const int t  = wrp + ti * 8;
        const int nt = n0 + t * dil;
        const float4 ql = *reinterpret_cast<const float4*>(
            g_qkv + (size_t)(b * N_ + nt) * QKVW + s * DH + lane * 4);
#pragma unroll
        for (int k = 0; k < KC; k++) {
            const float4 kf = *reinterpret_cast<const float4*>(&kv[t + k][lane * 4]);
            float p = ql.x*kf.x + ql.y*kf.y + ql.z*kf.z + ql.w*kf.w;
            p += __shfl_xor_sync(0xffffffffu, p, 16);
            p += __shfl_xor_sync(0xffffffffu, p, 8);
            p += __shfl_xor_sync(0xffffffffu, p, 4);
            p += __shfl_xor_sync(0xffffffffu, p, 2);
            p += __shfl_xor_sync(0xffffffffu, p, 1);
            if (lane == 0) ssc[t][k] = p;
        }
    }
    __syncthreads();

    const int hcnt = c_hcnt[s];
    for (int hi = 0; hi < hcnt; hi++) {
        const int h = c_hbase[s] + hi;

        for (int i = tid; i < KC * KC; i += 256)
            sks[i >> 5][i & 31] = Sk[(size_t)h * KC * KC + i];
        __syncthreads();

        for (int i = tid; i < 32 * KC; i += 256) {
            const int t = i & 31, j = i >> 5;
            float acc = Sb[h * KC + j];
#pragma unroll
            for (int k = 0; k < KC; k++) acc += ssc[t][k] * sks[j][k];
            shs[t][j] = acc;
        }
        __syncthreads();

        if (tid < 32) {
            float* rowp = shs[tid];
            float m = rowp[0];
#pragma unroll
            for (int j = 1; j < KC; j++) m = fmaxf(m, rowp[j]);
            float sum = 0.0f;
#pragma unroll
            for (int j = 0; j < KC; j++) { float e = expf(rowp[j]-m); rowp[j] = e; sum += e; }
            const float inv = 1.0f / sum;
#pragma unroll
            for (int j = 0; j < KC; j++) rowp[j] *= inv;
        }
        __syncthreads();

        for (int i = tid; i < 63 * DH; i += 256) {
            const int u = i >> 7, col = i & 127;
            const int idx = base + u * dil;
            kv[u][col] = (idx >= 0 && idx < N_)
                ? g_qkv[(size_t)(b * N_ + idx) * QKVW + VOFF + h * DH + col]
                : Vb[h * DH + col];
        }
        __syncthreads();

        const int dq = lane * 4;
#pragma unroll
        for (int tt = 0; tt < 4; tt++) {
            const int t  = wrp + tt * 8;
            const int nt = n0 + t * dil;
            float4 acc = {0.f, 0.f, 0.f, 0.f};
#pragma unroll
            for (int j = 0; j < KC; j++) {
                const float wv = shs[t][j];
                const float4 v = *reinterpret_cast<const float4*>(&kv[t + j][dq]);
                acc.x += wv * v.x; acc.y += wv * v.y;
                acc.z += wv * v.z; acc.w += wv * v.w;
            }
            const __half h0 = __float2half_rn(acc.x);
            const __half h1 = __float2half_rn(acc.y);
            const __half h2 = __float2half_rn(acc.z);
            const __half h3 = __float2half_rn(acc.w);
            const __half l0 = __float2half_rn(acc.x - __half2float(h0));
            const __half l1 = __float2half_rn(acc.y - __half2float(h1));
            const __half l2 = __float2half_rn(acc.z - __half2float(h2));
            const __half l3 = __float2half_rn(acc.w - __half2float(h3));
            __half2 hp0; hp0.x = h0; hp0.y = h1;
            __half2 hp1; hp1.x = h2; hp1.y = h3;
            __half2 lp0; lp0.x = l0; lp0.y = l1;
            __half2 lp1; lp1.x = l2; lp1.y = l3;
            uint2 hv, lv;
            hv.x = *reinterpret_cast<uint32_t*>(&hp0);
            hv.y = *reinterpret_cast<uint32_t*>(&hp1);
            lv.x = *reinterpret_cast<uint32_t*>(&lp0);
            lv.y = *reinterpret_cast<uint32_t*>(&lp1);
            __half* orow = gb_at + (size_t)(b * N_ + nt) * KE_C;
            const int col = h * DH + dq;
            *reinterpret_cast<uint2*>(orow + col)      = hv;
            *reinterpret_cast<uint2*>(orow + VW + col) = lv;
        }
        __syncthreads();
    }
}

extern "C" void kernel_launch(void* const* d_in, const int* in_sizes, int n_in,
                              void* d_out, int out_size)
{
    const float* query = (const float*)d_in[0];
    const float* key   = (const float*)d_in[1];
    const float* value = (const float*)d_in[2];
    const float* Qk    = (const float*)d_in[3];
    const float* Qb    = (const float*)d_in[4];
    const float* Kk    = (const float*)d_in[5];
    const float* Kb    = (const float*)d_in[6];
    const float* Vk    = (const float*)d_in[7];
    const float* Vb    = (const float*)d_in[8];
    const float* Sk    = (const float*)d_in[9];
    const float* Sb    = (const float*)d_in[10];
    const float* Ck    = (const float*)d_in[11];
    const float* Cb    = (const float*)d_in[12];
    float* out = (float*)d_out;

    cudaFuncSetAttribute(hmma_qkv_kernel,
        cudaFuncAttributeMaxDynamicSharedMemorySize, SMEM_GEMM);
    cudaFuncSetAttribute(hmma_col_kernel,
        cudaFuncAttributeMaxDynamicSharedMemorySize, SMEM_GEMM);

    const int M = B_ * N_;  // 2048

    {   // pre-init out with bias (collapse accumulates atomically)
        init_out_kernel<<<(M * DM / 4) / 256, 256>>>(Cb, out);
    }
    {   // activations q/k/v [xh|xl] in one launch
        const int pairs = M * DM / 2;
        dim3 grid((pairs + 255) / 256, 3);
        cvt_qkv_kernel<<<grid, 256>>>(query, key, value);
    }
    {   // merged weight conversions (Qk|Kk|Vk then Ck), one launch
        const int pairs = WPAIRS + CPAIRS;
        cvt_wts_kernel<<<(pairs + 255) / 256, 256>>>(Qk, Kk, Vk, Ck);
    }
    {   // fused Q|K|V projection: grid (24, 16) = 384 CTAs, 3 CTAs/SM
        dim3 grid(QKVW / 128, M / 128);
        hmma_qkv_kernel<<<grid, 128, SMEM_GEMM>>>(Qb, Kb, Vb);
    }
    {   // fused banded attention: grid (32, SH, B)
        dim3 grid(32, SH, B_);
        attn_fused_kernel<<<grid, 256>>>(Kb, Vb, Sk, Sb);
    }
    {   // collapse split-K=4, atomic accumulate into out: grid (5, 16, 4)
        dim3 grid(DM / 128, M / 128, ZSPLIT);
        hmma_col_kernel<<<grid, 128, SMEM_GEMM>>>(out);
    }
}

// round 15
// speedup vs baseline: 1.1900x; 1.1232x over previous
#include <cuda_runtime.h>
#include <cuda_fp16.h>
#include <cstdint>

#define B_    2
#define N_    1024
#define DM    640
#define SH    5
#define DH    128
#define NH    14
#define KC    32
#define VW    (NH * DH)       // 1792
#define QKVW  3072
#define KOFF  640
#define VOFF  1280
#define KE_P  (2 * DM)        // 1280  [xh|xl] / [yh|yh]
#define ZSPLIT 4

// -------- device scratch --------
__device__ float g_qkv [B_ * N_ * QKVW];
__device__ float g_part[ZSPLIT * B_ * N_ * DM];

__device__ __half gb_q [B_ * N_ * KE_P];
__device__ __half gb_k [B_ * N_ * KE_P];
__device__ __half gb_v [B_ * N_ * KE_P];
__device__ __half gb_w [QKVW * KE_P];
__device__ __half gb_Ck[DM * VW];        // plain fp16
__device__ __half gb_at[B_ * N_ * VW];   // plain fp16 attention output

__constant__ int c_dil  [SH] = {1, 1, 2, 4, 8};
__constant__ int c_hbase[SH] = {0, 5, 10, 12, 13};
__constant__ int c_hcnt [SH] = {5, 5, 2, 1, 1};

// ============================ helpers ======================================
__device__ __forceinline__ uint32_t smem_u32(const void* p) {
    return (uint32_t)__cvta_generic_to_shared(p);
}
__device__ __forceinline__ void cp_async16(uint32_t saddr, const void* g) {
    asm volatile("cp.async.cg.shared.global [%0], [%1], 16;"
                 :: "r"(saddr), "l"(g) : "memory");
}
#define CP_COMMIT() asm volatile("cp.async.commit_group;" ::: "memory")
#define CP_WAIT1()  asm volatile("cp.async.wait_group 1;"  ::: "memory")
#define CP_WAIT0()  asm volatile("cp.async.wait_group 0;"  ::: "memory")

__device__ __forceinline__ void ldmx4(uint32_t* r, uint32_t a) {
    asm volatile("ldmatrix.sync.aligned.m8n8.x4.shared.b16 {%0,%1,%2,%3}, [%4];"
        : "=r"(r[0]), "=r"(r[1]), "=r"(r[2]), "=r"(r[3]) : "r"(a));
}
__device__ __forceinline__ void mma16816(float* d, const uint32_t* a,
                                         const uint32_t b0, const uint32_t b1) {
    asm volatile(
        "mma.sync.aligned.m16n8k16.row.col.f32.f16.f16.f32 "
        "{%0,%1,%2,%3}, {%4,%5,%6,%7}, {%8,%9}, {%0,%1,%2,%3};"
        : "+f"(d[0]), "+f"(d[1]), "+f"(d[2]), "+f"(d[3])
        : "r"(a[0]), "r"(a[1]), "r"(a[2]), "r"(a[3]), "r"(b0), "r"(b1));
}

// ---------------------------------------------------------------------------
// HMMA fp16 GEMM (R11 exact mainloop). 128x128 CTA tile, 128 threads,
// BK=32, 3-stage cp.async pipeline. 61.4 KB smem -> 3 CTAs/SM.
// ---------------------------------------------------------------------------
#define BKT   32
#define LDS_  40                 // 32 + 8 pad (fp16 elems)
#define TSZ   (128 * LDS_ * 2)   // 10240 B per tile
#define STAGE (2 * TSZ)          // 20480 B (A + B)
#define SMEM_GEMM (3 * STAGE)    // 61440 B

__device__ __forceinline__ void hmma_gemm_body(
    const __half* __restrict__ A, const __half* __restrict__ W,
    const float* __restrict__ bias_tile, float* __restrict__ C,
    int nk, int lda, int ldw, int ldc)
{
    extern __shared__ char smem[];
    const uint32_t smb = smem_u32(smem);

    const int bm = blockIdx.y * 128;
    const int bn = blockIdx.x * 128;
    const int tid = threadIdx.x;                 // 0..127
    const int lane = tid & 31, wid = tid >> 5;   // 4 warps
    const int wm = (wid & 1) * 64;
    const int wn = (wid >> 1) * 64;

    float acc[4][8][4] = {};

    auto issue = [&](int it2) {
        if (it2 < nk) {
            const uint32_t st = smb + (it2 % 3) * STAGE;
            const int cb = it2 * BKT;
#pragma unroll
            for (int i = 0; i < 4; i++) {
                const int idx = tid + i * 128;
                const int row = idx >> 2;           // 0..127
                const int col = (idx & 3) * 8;      // 0,8,16,24
                const uint32_t so = (uint32_t)(row * LDS_ + col) * 2;
                cp_async16(st +       so, A + (size_t)(bm + row) * lda + cb + col);
                cp_async16(st + TSZ + so, W + (size_t)(bn + row) * ldw + cb + col);
            }
        }
        CP_COMMIT();
    };

    issue(0);
    issue(1);

    const int a_row = wm + (lane & 15);
    const int a_kof = (lane >> 4) * 8;
    const int b_row = wn + (lane & 7) + (lane >> 4) * 8;
    const int b_kof = ((lane >> 3) & 1) * 8;

    for (int it = 0; it < nk; ++it) {
        CP_WAIT1();
        __syncthreads();
        issue(it + 2);

        const uint32_t st = smb + (it % 3) * STAGE;
        const uint32_t sA = st;
        const uint32_t sB = st + TSZ;
#pragma unroll
        for (int ks = 0; ks < 2; ++ks) {
            const int k0 = ks * 16;
            uint32_t af[4][4], bf[4][4];
#pragma unroll
            for (int mi = 0; mi < 4; mi++)
                ldmx4(af[mi], sA + (uint32_t)((a_row + mi * 16) * LDS_ + k0 + a_kof) * 2);
#pragma unroll
            for (int g2 = 0; g2 < 4; g2++)
                ldmx4(bf[g2], sB + (uint32_t)((b_row + g2 * 16) * LDS_ + k0 + b_kof) * 2);
#pragma unroll
            for (int mi = 0; mi < 4; mi++)
#pragma unroll
                for (int ni = 0; ni < 8; ni++)
                    mma16816(acc[mi][ni], af[mi],
                             bf[ni >> 1][(ni & 1) * 2], bf[ni >> 1][(ni & 1) * 2 + 1]);
        }
    }

    const int g = lane >> 2, t = lane & 3;
#pragma unroll
    for (int mi = 0; mi < 4; mi++) {
        const int row0 = bm + wm + mi * 16 + g;
#pragma unroll
        for (int ni = 0; ni < 8; ni++) {
            const int colL = wn + ni * 8 + t * 2;
            float b0 = 0.f, b1 = 0.f;
            if (bias_tile) { b0 = bias_tile[colL]; b1 = bias_tile[colL + 1]; }
            float2 v0 = {acc[mi][ni][0] + b0, acc[mi][ni][1] + b1};
            float2 v1 = {acc[mi][ni][2] + b0, acc[mi][ni][3] + b1};
            *reinterpret_cast<float2*>(&C[(size_t)row0 * ldc + bn + colL]) = v0;
            *reinterpret_cast<float2*>(&C[(size_t)(row0 + 8) * ldc + bn + colL]) = v1;
        }
    }
}

__global__ __launch_bounds__(128, 3) void hmma_qkv_kernel(
    const float* __restrict__ Qb, const float* __restrict__ Kb,
    const float* __restrict__ Vb)
{
    const int bn = blockIdx.x * 128;
    const __half* A = (bn < KOFF) ? gb_q : (bn < VOFF) ? gb_k : gb_v;
    const float* bias = (bn < KOFF) ? (Qb + bn)
                      : (bn < VOFF) ? (Kb + bn - KOFF)
                                    : (Vb + bn - VOFF);
    hmma_gemm_body(A, gb_w, bias, g_qkv, KE_P / BKT, KE_P, KE_P, QKVW);
}

__global__ __launch_bounds__(128, 3) void hmma_col_kernel()
{
    const int z = blockIdx.z;            // 56 chunks of 32: 14 per z
    const int cstart = z * 14;
    hmma_gemm_body(gb_at + cstart * BKT, gb_Ck + cstart * BKT, nullptr,
                   g_part + (size_t)z * (B_ * N_ * DM),
                   14, VW, VW, DM);
}

// ---------------------------------------------------------------------------
// fp32 -> fp16 conversions
// ---------------------------------------------------------------------------
__device__ __forceinline__ void cvt_act(
    const float* __restrict__ inrow, __half* __restrict__ outrow, int k, int K)
{
    const float2 x = reinterpret_cast<const float2*>(inrow)[k];
    const __half h0 = __float2half_rn(x.x);
    const __half h1 = __float2half_rn(x.y);
    const __half l0 = __float2half_rn(x.x - __half2float(h0));
    const __half l1 = __float2half_rn(x.y - __half2float(h1));
    __half2 hh; hh.x = h0; hh.y = h1;
    __half2 ll; ll.x = l0; ll.y = l1;
    __half2* orow = reinterpret_cast<__half2*>(outrow);
    orow[k] = hh;
    orow[(K >> 1) + k] = ll;
}
__device__ __forceinline__ void cvt_wt(
    const float* __restrict__ inrow, __half* __restrict__ outrow, int k, int K)
{
    const float2 x = reinterpret_cast<const float2*>(inrow)[k];
    __half2 hh; hh.x = __float2half_rn(x.x); hh.y = __float2half_rn(x.y);
    __half2* orow = reinterpret_cast<__half2*>(outrow);
    orow[k] = hh;
    orow[(K >> 1) + k] = hh;     // duplicate hi
}

__global__ __launch_bounds__(256) void cvt_qkv_kernel(
    const float* __restrict__ q, const float* __restrict__ k,
    const float* __restrict__ v)
{
    const int i = blockIdx.x * 256 + threadIdx.x;
    if (i >= B_ * N_ * DM / 2) return;
    const int which = blockIdx.y;
    const float* in = (which == 0) ? q : (which == 1) ? k : v;
    __half* out = (which == 0) ? gb_q : (which == 1) ? gb_k : gb_v;
    const int r = i / (DM / 2), kk = i % (DM / 2);
    cvt_act(in + (size_t)r * DM, out + (size_t)r * KE_P, kk, DM);
}

#define WPAIRS (QKVW * DM / 2)
#define CPAIRS (DM * VW / 2)
__global__ __launch_bounds__(256) void cvt_wts_kernel(
    const float* __restrict__ Qk, const float* __restrict__ Kk,
    const float* __restrict__ Vk, const float* __restrict__ Ck)
{
    const int i = blockIdx.x * 256 + threadIdx.x;
    if (i < WPAIRS) {
        const int r = i / (DM / 2), kk = i % (DM / 2);
        const float* src = (r < KOFF) ? (Qk + (size_t)r * DM)
                         : (r < VOFF) ? (Kk + (size_t)(r - KOFF) * DM)
                                      : (Vk + (size_t)(r - VOFF) * DM);
        cvt_wt(src, gb_w + (size_t)r * KE_P, kk, DM);
    } else if (i < WPAIRS + CPAIRS) {
        const int j = i - WPAIRS;
        const float2 x = reinterpret_cast<const float2*>(Ck)[j];
        __half2 hh; hh.x = __float2half_rn(x.x); hh.y = __float2half_rn(x.y);
        reinterpret_cast<__half2*>(gb_Ck)[j] = hh;
    }
}

__global__ __launch_bounds__(256) void add_bias_kernel(
    const float* __restrict__ Cb, float* __restrict__ out)
{
    const int i = blockIdx.x * 256 + threadIdx.x;
    const float4 p0 = reinterpret_cast<const float4*>(g_part)[i];
    const float4 p1 = reinterpret_cast<const float4*>(g_part + (size_t)B_ * N_ * DM)[i];
    const float4 p2 = reinterpret_cast<const float4*>(g_part + (size_t)2 * B_ * N_ * DM)[i];
    const float4 p3 = reinterpret_cast<const float4*>(g_part + (size_t)3 * B_ * N_ * DM)[i];
    const float4 bb = reinterpret_cast<const float4*>(Cb)[i % (DM / 4)];
    float4 o = {p0.x + p1.x + p2.x + p3.x + bb.x,
                p0.y + p1.y + p2.y + p3.y + bb.y,
                p0.z + p1.z + p2.z + p3.z + bb.z,
                p0.w + p1.w + p2.w + p3.w + bb.w};
    reinterpret_cast<float4*>(out)[i] = o;
}

// ---------------------------------------------------------------------------
// Fused banded attention with cp.async double-buffered K/V tiles.
// Grid (32, SH, B), 256 threads. Dynamic smem layout (floats):
//   kv0 @ 0, kv1 @ 8064, ssc @ 16128 (33/row), sks @ 17184, shs @ 18208 (33/row)
// ---------------------------------------------------------------------------
#define ATN_KV0  0
#define ATN_KV1  8064
#define ATN_SSC  16128
#define ATN_SKS  17184
#define ATN_SHS  18208
#define SMEM_ATTN ((18208 + 1056) * 4)    // 77056 B

__global__ __launch_bounds__(256) void attn_fused_kernel(
    const float* __restrict__ Kb, const float* __restrict__ Vb,
    const float* __restrict__ Sk, const float* __restrict__ Sb)
{
    extern __shared__ float sm[];
    float* kvb[2] = { sm + ATN_KV0, sm + ATN_KV1 };
    float* ssc = sm + ATN_SSC;
    float* sks = sm + ATN_SKS;
    float* shs = sm + ATN_SHS;

    const int z   = blockIdx.x;
    const int s   = blockIdx.y;
    const int b   = blockIdx.z;
    const int tid = threadIdx.x;
    const int lane = tid & 31;
    const int wrp  = tid >> 5;

    const int dil = c_dil[s];
    const int pl  = ((KC - 1) * dil) >> 1;
    const int cpr = 32 / dil;
    const int r0  = z / cpr;
    const int c0  = z % cpr;
    const int n0  = r0 + c0 * 32 * dil;
    const int base = n0 - pl;

    // cp.async a 63x128 f32 band tile from g_qkv (or bias row when OOB)
    auto issue_tile = [&](float* dst, int off, const float* bias_row) {
        for (int i = tid; i < 63 * 32; i += 256) {
            const int u  = i >> 5;
            const int c4 = (i & 31) * 4;
            const int idx = base + u * dil;
            const float* src = (idx >= 0 && idx < N_)
                ? g_qkv + (size_t)(b * N_ + idx) * QKVW + off + c4
                : bias_row + c4;
            cp_async16(smem_u32(dst + u * DH + c4), src);
        }
    };

    const int hbase = c_hbase[s];
    const int hcnt  = c_hcnt[s];

    issue_tile(kvb[0], KOFF + s * DH, Kb + s * DH);   // K tile
    CP_COMMIT();
    issue_tile(kvb[1], VOFF + hbase * DH, Vb + hbase * DH);   // V(h0)
    CP_COMMIT();

    CP_WAIT1();          // K tile ready
    __syncthreads();

    // ---- scores from kvb[0] ----
#pragma unroll
    for (int ti = 0; ti < 4; ti++) {
        const int t  = wrp + ti * 8;
        const int nt = n0 + t * dil;
        const float4 ql = *reinterpret_cast<const float4*>(
            g_qkv + (size_t)(b * N_ + nt) * QKVW + s * DH + lane * 4);
#pragma unroll
        for (int k = 0; k < KC; k++) {
            const float4 kf = *reinterpret_cast<const float4*>(
                kvb[0] + (t + k) * DH + lane * 4);
            float p = ql.x*kf.x + ql.y*kf.y + ql.z*kf.z + ql.w*kf.w;
            p += __shfl_xor_sync(0xffffffffu, p, 16);
            p += __shfl_xor_sync(0xffffffffu, p, 8);
            p += __shfl_xor_sync(0xffffffffu, p, 4);
            p += __shfl_xor_sync(0xffffffffu, p, 2);
            p += __shfl_xor_sync(0xffffffffu, p, 1);
            if (lane == 0) ssc[t * 33 + k] = p;
        }
    }
    __syncthreads();

    int cur = 1;
    for (int hi = 0; hi < hcnt; hi++) {
        const int h = hbase + hi;

        // load Sk[h]
        for (int i = tid; i < KC * KC; i += 256)
            sks[i] = Sk[(size_t)h * KC * KC + i];
        __syncthreads();

        // Pos_Sampling
        for (int i = tid; i < 32 * KC; i += 256) {
            const int t = i & 31, j = i >> 5;
            float acc = Sb[h * KC + j];
#pragma unroll
            for (int k = 0; k < KC; k++) acc += ssc[t * 33 + k] * sks[j * 32 + k];
            shs[t * 33 + j] = acc;
        }
        __syncthreads();

        // softmax per row
        if (tid < 32) {
            float* rowp = shs + tid * 33;
            float m = rowp[0];
#pragma unroll
            for (int j = 1; j < KC; j++) m = fmaxf(m, rowp[j]);
            float sum = 0.0f;
#pragma unroll
            for (int j = 0; j < KC; j++) { float e = expf(rowp[j]-m); rowp[j] = e; sum += e; }
            const float inv = 1.0f / sum;
#pragma unroll
            for (int j = 0; j < KC; j++) rowp[j] *= inv;
        }

        CP_WAIT0();          // V(hi) in kvb[cur] ready
        __syncthreads();     // also publishes softmax

        // prefetch V(hi+1) into the other buffer (done with it after scores/apply)
        if (hi + 1 < hcnt)
            issue_tile(kvb[cur ^ 1], VOFF + (h + 1) * DH, Vb + (h + 1) * DH);
        CP_COMMIT();

        // apply + write fp16 to gb_at
        const float* kv = kvb[cur];
        const int dq = lane * 4;
#pragma unroll
        for (int tt = 0; tt < 4; tt++) {
            const int t  = wrp + tt * 8;
            const int nt = n0 + t * dil;
            float4 acc = {0.f, 0.f, 0.f, 0.f};
#pragma unroll
            for (int j = 0; j < KC; j++) {
                const float wv = shs[t * 33 + j];
                const float4 v = *reinterpret_cast<const float4*>(
                    kv + (t + j) * DH + dq);
                acc.x += wv * v.x; acc.y += wv * v.y;
                acc.z += wv * v.z; acc.w += wv * v.w;
            }
            __half2 hp0; hp0.x = __float2half_rn(acc.x); hp0.y = __float2half_rn(acc.y);
            __half2 hp1; hp1.x = __float2half_rn(acc.z); hp1.y = __float2half_rn(acc.w);
            uint2 hv;
            hv.x = *reinterpret_cast<uint32_t*>(&hp0);
            hv.y = *reinterpret_cast<uint32_t*>(&hp1);
            *reinterpret_cast<uint2*>(
                gb_at + (size_t)(b * N_ + nt) * VW + h * DH + dq) = hv;
        }
        __syncthreads();
        cur ^= 1;
    }
}

extern "C" void kernel_launch(void* const* d_in, const int* in_sizes, int n_in,
                              void* d_out, int out_size)
{
    const float* query = (const float*)d_in[0];
    const float* key   = (const float*)d_in[1];
    const float* value = (const float*)d_in[2];
    const float* Qk    = (const float*)d_in[3];
    const float* Qb    = (const float*)d_in[4];
    const float* Kk    = (const float*)d_in[5];
    const float* Kb    = (const float*)d_in[6];
    const float* Vk    = (const float*)d_in[7];
    const float* Vb    = (const float*)d_in[8];
    const float* Sk    = (const float*)d_in[9];
    const float* Sb    = (const float*)d_in[10];
    const float* Ck    = (const float*)d_in[11];
    const float* Cb    = (const float*)d_in[12];
    float* out = (float*)d_out;

    cudaFuncSetAttribute(hmma_qkv_kernel,
        cudaFuncAttributeMaxDynamicSharedMemorySize, SMEM_GEMM);
    cudaFuncSetAttribute(hmma_col_kernel,
        cudaFuncAttributeMaxDynamicSharedMemorySize, SMEM_GEMM);
    cudaFuncSetAttribute(attn_fused_kernel,
        cudaFuncAttributeMaxDynamicSharedMemorySize, SMEM_ATTN);

    const int M = B_ * N_;  // 2048

    {   // activations q/k/v [xh|xl] in one launch
        const int pairs = M * DM / 2;
        dim3 grid((pairs + 255) / 256, 3);
        cvt_qkv_kernel<<<grid, 256>>>(query, key, value);
    }
    {   // merged weight conversions
        const int pairs = WPAIRS + CPAIRS;
        cvt_wts_kernel<<<(pairs + 255) / 256, 256>>>(Qk, Kk, Vk, Ck);
    }
    {   // fused Q|K|V projection: grid (24, 16) = 384 CTAs, 3 CTAs/SM
        dim3 grid(QKVW / 128, M / 128);
        hmma_qkv_kernel<<<grid, 128, SMEM_GEMM>>>(Qb, Kb, Vb);
    }
    {   // fused banded attention with async prefetch: grid (32, SH, B)
        dim3 grid(32, SH, B_);
        attn_fused_kernel<<<grid, 256, SMEM_ATTN>>>(Kb, Vb, Sk, Sb);
    }
    {   // collapse split-K=4 over fp16 gb_at: grid (5, 16, 4)
        dim3 grid(DM / 128, M / 128, ZSPLIT);
        hmma_col_kernel<<<grid, 128, SMEM_GEMM>>>();
    }
    add_bias_kernel<<<(M * DM / 4) / 256, 256>>>(Cb, out);
}

// round 16
// speedup vs baseline: 1.2074x; 1.0146x over previous
#include <cuda_runtime.h>
#include <cuda_fp16.h>
#include <cstdint>

#define B_    2
#define N_    1024
#define DM    640
#define SH    5
#define DH    128
#define NH    14
#define KC    32
#define VW    (NH * DH)       // 1792
#define QKVW  3072
#define KOFF  640
#define VOFF  1280
#define KE_P  (2 * DM)        // 1280  [xh|xl] / [yh|yh]
#define ZSPLIT 4

// -------- device scratch --------
__device__ float g_qkv [B_ * N_ * QKVW];
__device__ float g_part[ZSPLIT * B_ * N_ * DM];

__device__ __half gb_q [B_ * N_ * KE_P];
__device__ __half gb_k [B_ * N_ * KE_P];
__device__ __half gb_v [B_ * N_ * KE_P];
__device__ __half gb_w [QKVW * KE_P];
__device__ __half gb_Ck[DM * VW];        // plain fp16
__device__ __half gb_at[B_ * N_ * VW];   // plain fp16 attention output

__constant__ int c_dil  [SH] = {1, 1, 2, 4, 8};
// balanced head groups, heavy first: (subhead, first head, head count)
__constant__ int c_gs[7] = {0, 1, 0, 1, 2, 3, 4};
__constant__ int c_gh[7] = {0, 5, 3, 8, 10, 12, 13};
__constant__ int c_gn[7] = {3, 3, 2, 2, 2, 1, 1};

// ============================ helpers ======================================
__device__ __forceinline__ uint32_t smem_u32(const void* p) {
    return (uint32_t)__cvta_generic_to_shared(p);
}
__device__ __forceinline__ void cp_async16(uint32_t saddr, const void* g) {
    asm volatile("cp.async.cg.shared.global [%0], [%1], 16;"
                 :: "r"(saddr), "l"(g) : "memory");
}
#define CP_COMMIT() asm volatile("cp.async.commit_group;" ::: "memory")
#define CP_WAIT1()  asm volatile("cp.async.wait_group 1;"  ::: "memory")
#define CP_WAIT0()  asm volatile("cp.async.wait_group 0;"  ::: "memory")

__device__ __forceinline__ void ldmx4(uint32_t* r, uint32_t a) {
    asm volatile("ldmatrix.sync.aligned.m8n8.x4.shared.b16 {%0,%1,%2,%3}, [%4];"
        : "=r"(r[0]), "=r"(r[1]), "=r"(r[2]), "=r"(r[3]) : "r"(a));
}
__device__ __forceinline__ void mma16816(float* d, const uint32_t* a,
                                         const uint32_t b0, const uint32_t b1) {
    asm volatile(
        "mma.sync.aligned.m16n8k16.row.col.f32.f16.f16.f32 "
        "{%0,%1,%2,%3}, {%4,%5,%6,%7}, {%8,%9}, {%0,%1,%2,%3};"
        : "+f"(d[0]), "+f"(d[1]), "+f"(d[2]), "+f"(d[3])
        : "r"(a[0]), "r"(a[1]), "r"(a[2]), "r"(a[3]), "r"(b0), "r"(b1));
}

// ---------------------------------------------------------------------------
// HMMA fp16 GEMM (R11 exact mainloop). 128x128 CTA tile, 128 threads,
// BK=32, 3-stage cp.async pipeline. 61.4 KB smem -> 3 CTAs/SM.
// ---------------------------------------------------------------------------
#define BKT   32
#define LDS_  40                 // 32 + 8 pad (fp16 elems)
#define TSZ   (128 * LDS_ * 2)   // 10240 B per tile
#define STAGE (2 * TSZ)          // 20480 B (A + B)
#define SMEM_GEMM (3 * STAGE)    // 61440 B

__device__ __forceinline__ void hmma_gemm_body(
    const __half* __restrict__ A, const __half* __restrict__ W,
    const float* __restrict__ bias_tile, float* __restrict__ C,
    int nk, int lda, int ldw, int ldc)
{
    extern __shared__ char smem[];
    const uint32_t smb = smem_u32(smem);

    const int bm = blockIdx.y * 128;
    const int bn = blockIdx.x * 128;
    const int tid = threadIdx.x;                 // 0..127
    const int lane = tid & 31, wid = tid >> 5;   // 4 warps
    const int wm = (wid & 1) * 64;
    const int wn = (wid >> 1) * 64;

    float acc[4][8][4] = {};

    auto issue = [&](int it2) {
        if (it2 < nk) {
            const uint32_t st = smb + (it2 % 3) * STAGE;
            const int cb = it2 * BKT;
#pragma unroll
            for (int i = 0; i < 4; i++) {
                const int idx = tid + i * 128;
                const int row = idx >> 2;           // 0..127
                const int col = (idx & 3) * 8;      // 0,8,16,24
                const uint32_t so = (uint32_t)(row * LDS_ + col) * 2;
                cp_async16(st +       so, A + (size_t)(bm + row) * lda + cb + col);
                cp_async16(st + TSZ + so, W + (size_t)(bn + row) * ldw + cb + col);
            }
        }
        CP_COMMIT();
    };

    issue(0);
    issue(1);

    const int a_row = wm + (lane & 15);
    const int a_kof = (lane >> 4) * 8;
    const int b_row = wn + (lane & 7) + (lane >> 4) * 8;
    const int b_kof = ((lane >> 3) & 1) * 8;

    for (int it = 0; it < nk; ++it) {
        CP_WAIT1();
        __syncthreads();
        issue(it + 2);

        const uint32_t st = smb + (it % 3) * STAGE;
        const uint32_t sA = st;
        const uint32_t sB = st + TSZ;
#pragma unroll
        for (int ks = 0; ks < 2; ++ks) {
            const int k0 = ks * 16;
            uint32_t af[4][4], bf[4][4];
#pragma unroll
            for (int mi = 0; mi < 4; mi++)
                ldmx4(af[mi], sA + (uint32_t)((a_row + mi * 16) * LDS_ + k0 + a_kof) * 2);
#pragma unroll
            for (int g2 = 0; g2 < 4; g2++)
                ldmx4(bf[g2], sB + (uint32_t)((b_row + g2 * 16) * LDS_ + k0 + b_kof) * 2);
#pragma unroll
            for (int mi = 0; mi < 4; mi++)
#pragma unroll
                for (int ni = 0; ni < 8; ni++)
                    mma16816(acc[mi][ni], af[mi],
                             bf[ni >> 1][(ni & 1) * 2], bf[ni >> 1][(ni & 1) * 2 + 1]);
        }
    }

    const int g = lane >> 2, t = lane & 3;
#pragma unroll
    for (int mi = 0; mi < 4; mi++) {
        const int row0 = bm + wm + mi * 16 + g;
#pragma unroll
        for (int ni = 0; ni < 8; ni++) {
            const int colL = wn + ni * 8 + t * 2;
            float b0 = 0.f, b1 = 0.f;
            if (bias_tile) { b0 = bias_tile[colL]; b1 = bias_tile[colL + 1]; }
            float2 v0 = {acc[mi][ni][0] + b0, acc[mi][ni][1] + b1};
            float2 v1 = {acc[mi][ni][2] + b0, acc[mi][ni][3] + b1};
            *reinterpret_cast<float2*>(&C[(size_t)row0 * ldc + bn + colL]) = v0;
            *reinterpret_cast<float2*>(&C[(size_t)(row0 + 8) * ldc + bn + colL]) = v1;
        }
    }
}

__global__ __launch_bounds__(128, 3) void hmma_qkv_kernel(
    const float* __restrict__ Qb, const float* __restrict__ Kb,
    const float* __restrict__ Vb)
{
    const int bn = blockIdx.x * 128;
    const __half* A = (bn < KOFF) ? gb_q : (bn < VOFF) ? gb_k : gb_v;
    const float* bias = (bn < KOFF) ? (Qb + bn)
                      : (bn < VOFF) ? (Kb + bn - KOFF)
                                    : (Vb + bn - VOFF);
    hmma_gemm_body(A, gb_w, bias, g_qkv, KE_P / BKT, KE_P, KE_P, QKVW);
}

__global__ __launch_bounds__(128, 3) void hmma_col_kernel()
{
    const int z = blockIdx.z;            // 56 chunks of 32: 14 per z
    const int cstart = z * 14;
    hmma_gemm_body(gb_at + cstart * BKT, gb_Ck + cstart * BKT, nullptr,
                   g_part + (size_t)z * (B_ * N_ * DM),
                   14, VW, VW, DM);
}

// ---------------------------------------------------------------------------
// fp32 -> fp16 conversions
// ---------------------------------------------------------------------------
__device__ __forceinline__ void cvt_act(
    const float* __restrict__ inrow, __half* __restrict__ outrow, int k, int K)
{
    const float2 x = reinterpret_cast<const float2*>(inrow)[k];
    const __half h0 = __float2half_rn(x.x);
    const __half h1 = __float2half_rn(x.y);
    const __half l0 = __float2half_rn(x.x - __half2float(h0));
    const __half l1 = __float2half_rn(x.y - __half2float(h1));
    __half2 hh; hh.x = h0; hh.y = h1;
    __half2 ll; ll.x = l0; ll.y = l1;
    __half2* orow = reinterpret_cast<__half2*>(outrow);
    orow[k] = hh;
    orow[(K >> 1) + k] = ll;
}
__device__ __forceinline__ void cvt_wt(
    const float* __restrict__ inrow, __half* __restrict__ outrow, int k, int K)
{
    const float2 x = reinterpret_cast<const float2*>(inrow)[k];
    __half2 hh; hh.x = __float2half_rn(x.x); hh.y = __float2half_rn(x.y);
    __half2* orow = reinterpret_cast<__half2*>(outrow);
    orow[k] = hh;
    orow[(K >> 1) + k] = hh;     // duplicate hi
}

__global__ __launch_bounds__(256) void cvt_qkv_kernel(
    const float* __restrict__ q, const float* __restrict__ k,
    const float* __restrict__ v)
{
    const int i = blockIdx.x * 256 + threadIdx.x;
    if (i >= B_ * N_ * DM / 2) return;
    const int which = blockIdx.y;
    const float* in = (which == 0) ? q : (which == 1) ? k : v;
    __half* out = (which == 0) ? gb_q : (which == 1) ? gb_k : gb_v;
    const int r = i / (DM / 2), kk = i % (DM / 2);
    cvt_act(in + (size_t)r * DM, out + (size_t)r * KE_P, kk, DM);
}

#define WPAIRS (QKVW * DM / 2)
#define CPAIRS (DM * VW / 2)
__global__ __launch_bounds__(256) void cvt_wts_kernel(
    const float* __restrict__ Qk, const float* __restrict__ Kk,
    const float* __restrict__ Vk, const float* __restrict__ Ck)
{
    const int i = blockIdx.x * 256 + threadIdx.x;
    if (i < WPAIRS) {
        const int r = i / (DM / 2), kk = i % (DM / 2);
        const float* src = (r < KOFF) ? (Qk + (size_t)r * DM)
                         : (r < VOFF) ? (Kk + (size_t)(r - KOFF) * DM)
                                      : (Vk + (size_t)(r - VOFF) * DM);
        cvt_wt(src, gb_w + (size_t)r * KE_P, kk, DM);
    } else if (i < WPAIRS + CPAIRS) {
        const int j = i - WPAIRS;
        const float2 x = reinterpret_cast<const float2*>(Ck)[j];
        __half2 hh; hh.x = __float2half_rn(x.x); hh.y = __float2half_rn(x.y);
        reinterpret_cast<__half2*>(gb_Ck)[j] = hh;
    }
}

__global__ __launch_bounds__(256) void add_bias_kernel(
    const float* __restrict__ Cb, float* __restrict__ out)
{
    const int i = blockIdx.x * 256 + threadIdx.x;
    const float4 p0 = reinterpret_cast<const float4*>(g_part)[i];
    const float4 p1 = reinterpret_cast<const float4*>(g_part + (size_t)B_ * N_ * DM)[i];
    const float4 p2 = reinterpret_cast<const float4*>(g_part + (size_t)2 * B_ * N_ * DM)[i];
    const float4 p3 = reinterpret_cast<const float4*>(g_part + (size_t)3 * B_ * N_ * DM)[i];
    const float4 bb = reinterpret_cast<const float4*>(Cb)[i % (DM / 4)];
    float4 o = {p0.x + p1.x + p2.x + p3.x + bb.x,
                p0.y + p1.y + p2.y + p3.y + bb.y,
                p0.z + p1.z + p2.z + p3.z + bb.z,
                p0.w + p1.w + p2.w + p3.w + bb.w};
    reinterpret_cast<float4*>(out)[i] = o;
}

// ---------------------------------------------------------------------------
// Fused banded attention, balanced head-groups + fused PS/softmax.
// Grid (32, 7, B), 256 threads. Smem (floats):
//   kv0 @0 (8064), kv1 @8064 (8064), ssc @16128 (1056),
//   skt @17184 (3*1056 transposed Sk), shs @20352 (1056)
// ---------------------------------------------------------------------------
#define ATN_KV0  0
#define ATN_KV1  8064
#define ATN_SSC  16128
#define ATN_SKT  17184
#define ATN_SHS  20352
#define SMEM_ATTN ((20352 + 1056) * 4)    // 85632 B -> 2 CTAs/SM

__global__ __launch_bounds__(256) void attn_fused_kernel(
    const float* __restrict__ Kb, const float* __restrict__ Vb,
    const float* __restrict__ Sk, const float* __restrict__ Sb)
{
    extern __shared__ float sm[];
    float* kvb[2] = { sm + ATN_KV0, sm + ATN_KV1 };
    float* ssc = sm + ATN_SSC;
    float* skt = sm + ATN_SKT;
    float* shs = sm + ATN_SHS;

    const int z   = blockIdx.x;
    const int g   = blockIdx.y;
    const int b   = blockIdx.z;
    const int tid = threadIdx.x;
    const int lane = tid & 31;
    const int wrp  = tid >> 5;

    const int s     = c_gs[g];
    const int hbase = c_gh[g];
    const int hcnt  = c_gn[g];

    const int dil = c_dil[s];
    const int pl  = ((KC - 1) * dil) >> 1;
    const int cpr = 32 / dil;
    const int r0  = z / cpr;
    const int c0  = z % cpr;
    const int n0  = r0 + c0 * 32 * dil;
    const int base = n0 - pl;

    auto issue_tile = [&](float* dst, int off, const float* bias_row) {
        for (int i = tid; i < 63 * 32; i += 256) {
            const int u  = i >> 5;
            const int c4 = (i & 31) * 4;
            const int idx = base + u * dil;
            const float* src = (idx >= 0 && idx < N_)
                ? g_qkv + (size_t)(b * N_ + idx) * QKVW + off + c4
                : bias_row + c4;
            cp_async16(smem_u32(dst + u * DH + c4), src);
        }
    };

    issue_tile(kvb[0], KOFF + s * DH, Kb + s * DH);           // K tile
    CP_COMMIT();
    issue_tile(kvb[1], VOFF + hbase * DH, Vb + hbase * DH);   // V(h0)
    CP_COMMIT();

    // preload group Sk transposed: skt[hi][k*33 + j] = Sk[h][j][k]
    for (int hi = 0; hi < hcnt; hi++) {
        const float* skh = Sk + (size_t)(hbase + hi) * KC * KC;
        for (int i = tid; i < KC * KC; i += 256) {
            const int j = i >> 5, k = i & 31;
            skt[hi * 1056 + k * 33 + j] = skh[i];
        }
    }

    CP_WAIT1();          // K tile ready (V0 may still be in flight)
    __syncthreads();

    // ---- scores from kvb[0] ----
#pragma unroll
    for (int ti = 0; ti < 4; ti++) {
        const int t  = wrp + ti * 8;
        const int nt = n0 + t * dil;
        const float4 ql = *reinterpret_cast<const float4*>(
            g_qkv + (size_t)(b * N_ + nt) * QKVW + s * DH + lane * 4);
#pragma unroll
        for (int k = 0; k < KC; k++) {
            const float4 kf = *reinterpret_cast<const float4*>(
                kvb[0] + (t + k) * DH + lane * 4);
            float p = ql.x*kf.x + ql.y*kf.y + ql.z*kf.z + ql.w*kf.w;
            p += __shfl_xor_sync(0xffffffffu, p, 16);
            p += __shfl_xor_sync(0xffffffffu, p, 8);
            p += __shfl_xor_sync(0xffffffffu, p, 4);
            p += __shfl_xor_sync(0xffffffffu, p, 2);
            p += __shfl_xor_sync(0xffffffffu, p, 1);
            if (lane == 0) ssc[t * 33 + k] = p;
        }
    }
    __syncthreads();

    int cur = 1;
    for (int hi = 0; hi < hcnt; hi++) {
        const int h = hbase + hi;
        const float* skh = skt + hi * 1056;
        const float sb = Sb[h * KC + lane];

        // fused Pos_Sampling + softmax: warp handles rows t = wrp*4 + r
#pragma unroll
        for (int r = 0; r < 4; r++) {
            const int t = wrp * 4 + r;
            float acc = sb;
#pragma unroll
            for (int k = 0; k < KC; k++)
                acc += ssc[t * 33 + k] * skh[k * 33 + lane];
            float m = acc;
            m = fmaxf(m, __shfl_xor_sync(0xffffffffu, m, 16));
            m = fmaxf(m, __shfl_xor_sync(0xffffffffu, m, 8));
            m = fmaxf(m, __shfl_xor_sync(0xffffffffu, m, 4));
            m = fmaxf(m, __shfl_xor_sync(0xffffffffu, m, 2));
            m = fmaxf(m, __shfl_xor_sync(0xffffffffu, m, 1));
            const float e = expf(acc - m);
            float ssum = e;
            ssum += __shfl_xor_sync(0xffffffffu, ssum, 16);
            ssum += __shfl_xor_sync(0xffffffffu, ssum, 8);
            ssum += __shfl_xor_sync(0xffffffffu, ssum, 4);
            ssum += __shfl_xor_sync(0xffffffffu, ssum, 2);
            ssum += __shfl_xor_sync(0xffffffffu, ssum, 1);
            shs[t * 33 + lane] = e / ssum;
        }

        CP_WAIT0();          // V(hi) ready
        __syncthreads();     // publishes shs + V tile

        if (hi + 1 < hcnt)
            issue_tile(kvb[cur ^ 1], VOFF + (h + 1) * DH, Vb + (h + 1) * DH);
        CP_COMMIT();

        // apply + write fp16 to gb_at
        const float* kv = kvb[cur];
        const int dq = lane * 4;
#pragma unroll
        for (int tt = 0; tt < 4; tt++) {
            const int t  = wrp + tt * 8;
            const int nt = n0 + t * dil;
            float4 acc = {0.f, 0.f, 0.f, 0.f};
#pragma unroll
            for (int j = 0; j < KC; j++) {
                const float wv = shs[t * 33 + j];
                const float4 v = *reinterpret_cast<const float4*>(
                    kv + (t + j) * DH + dq);
                acc.x += wv * v.x; acc.y += wv * v.y;
                acc.z += wv * v.z; acc.w += wv * v.w;
            }
            __half2 hp0; hp0.x = __float2half_rn(acc.x); hp0.y = __float2half_rn(acc.y);
            __half2 hp1; hp1.x = __float2half_rn(acc.z); hp1.y = __float2half_rn(acc.w);
            uint2 hv;
            hv.x = *reinterpret_cast<uint32_t*>(&hp0);
            hv.y = *reinterpret_cast<uint32_t*>(&hp1);
            *reinterpret_cast<uint2*>(
                gb_at + (size_t)(b * N_ + nt) * VW + h * DH + dq) = hv;
        }
        __syncthreads();
        cur ^= 1;
    }
}

extern "C" void kernel_launch(void* const* d_in, const int* in_sizes, int n_in,
                              void* d_out, int out_size)
{
    const float* query = (const float*)d_in[0];
    const float* key   = (const float*)d_in[1];
    const float* value = (const float*)d_in[2];
    const float* Qk    = (const float*)d_in[3];
    const float* Qb    = (const float*)d_in[4];
    const float* Kk    = (const float*)d_in[5];
    const float* Kb    = (const float*)d_in[6];
    const float* Vk    = (const float*)d_in[7];
    const float* Vb    = (const float*)d_in[8];
    const float* Sk    = (const float*)d_in[9];
    const float* Sb    = (const float*)d_in[10];
    const float* Ck    = (const float*)d_in[11];
    const float* Cb    = (const float*)d_in[12];
    float* out = (float*)d_out;

    cudaFuncSetAttribute(hmma_qkv_kernel,
        cudaFuncAttributeMaxDynamicSharedMemorySize, SMEM_GEMM);
    cudaFuncSetAttribute(hmma_col_kernel,
        cudaFuncAttributeMaxDynamicSharedMemorySize, SMEM_GEMM);
    cudaFuncSetAttribute(attn_fused_kernel,
        cudaFuncAttributeMaxDynamicSharedMemorySize, SMEM_ATTN);

    const int M = B_ * N_;  // 2048

    {   // activations q/k/v [xh|xl] in one launch
        const int pairs = M * DM / 2;
        dim3 grid((pairs + 255) / 256, 3);
        cvt_qkv_kernel<<<grid, 256>>>(query, key, value);
    }
    {   // merged weight conversions
        const int pairs = WPAIRS + CPAIRS;
        cvt_wts_kernel<<<(pairs + 255) / 256, 256>>>(Qk, Kk, Vk, Ck);
    }
    {   // fused Q|K|V projection: grid (24, 16) = 384 CTAs, 3 CTAs/SM
        dim3 grid(QKVW / 128, M / 128);
        hmma_qkv_kernel<<<grid, 128, SMEM_GEMM>>>(Qb, Kb, Vb);
    }
    {   // balanced banded attention: grid (32, 7, B)
        dim3 grid(32, 7, B_);
        attn_fused_kernel<<<grid, 256, SMEM_ATTN>>>(Kb, Vb, Sk, Sb);
    }
    {   // collapse split-K=4 over fp16 gb_at: grid (5, 16, 4)
        dim3 grid(DM / 128, M / 128, ZSPLIT);
        hmma_col_kernel<<<grid, 128, SMEM_GEMM>>>();
    }
    add_bias_kernel<<<(M * DM / 4) / 256, 256>>>(Cb, out);
}

// round 17
// speedup vs baseline: 1.2081x; 1.0006x over previous
#include <cuda_runtime.h>
#include <cuda_fp16.h>
#include <cstdint>

#define B_    2
#define N_    1024
#define DM    640
#define SH    5
#define DH    128
#define NH    14
#define KC    32
#define VW    (NH * DH)       // 1792
#define QKVW  3072
#define KOFF  640
#define VOFF  1280
#define KE_P  (2 * DM)        // 1280  [xh|xl] / [yh|yh]
#define ZSPLIT 4

// -------- device scratch --------
__device__ float g_qkv [B_ * N_ * QKVW];
__device__ float g_part[ZSPLIT * B_ * N_ * DM];

__device__ __half gb_q [B_ * N_ * KE_P];
__device__ __half gb_k [B_ * N_ * KE_P];
__device__ __half gb_v [B_ * N_ * KE_P];
__device__ __half gb_w [QKVW * KE_P];
__device__ __half gb_Ck[DM * VW];        // plain fp16
__device__ __half gb_at[B_ * N_ * VW];   // plain fp16 attention output

__constant__ int c_dil  [SH] = {1, 1, 2, 4, 8};
// balanced head groups, heavy first: (subhead, first head, head count)
__constant__ int c_gs[7] = {0, 1, 0, 1, 2, 3, 4};
__constant__ int c_gh[7] = {0, 5, 3, 8, 10, 12, 13};
__constant__ int c_gn[7] = {3, 3, 2, 2, 2, 1, 1};

// ============================ helpers ======================================
__device__ __forceinline__ uint32_t smem_u32(const void* p) {
    return (uint32_t)__cvta_generic_to_shared(p);
}
__device__ __forceinline__ void cp_async16(uint32_t saddr, const void* g) {
    asm volatile("cp.async.cg.shared.global [%0], [%1], 16;"
                 :: "r"(saddr), "l"(g) : "memory");
}
#define CP_COMMIT() asm volatile("cp.async.commit_group;" ::: "memory")
#define CP_WAIT1()  asm volatile("cp.async.wait_group 1;"  ::: "memory")
#define CP_WAIT0()  asm volatile("cp.async.wait_group 0;"  ::: "memory")

__device__ __forceinline__ void ldmx4(uint32_t* r, uint32_t a) {
    asm volatile("ldmatrix.sync.aligned.m8n8.x4.shared.b16 {%0,%1,%2,%3}, [%4];"
        : "=r"(r[0]), "=r"(r[1]), "=r"(r[2]), "=r"(r[3]) : "r"(a));
}
__device__ __forceinline__ void mma16816(float* d, const uint32_t* a,
                                         const uint32_t b0, const uint32_t b1) {
    asm volatile(
        "mma.sync.aligned.m16n8k16.row.col.f32.f16.f16.f32 "
        "{%0,%1,%2,%3}, {%4,%5,%6,%7}, {%8,%9}, {%0,%1,%2,%3};"
        : "+f"(d[0]), "+f"(d[1]), "+f"(d[2]), "+f"(d[3])
        : "r"(a[0]), "r"(a[1]), "r"(a[2]), "r"(a[3]), "r"(b0), "r"(b1));
}

// ---------------------------------------------------------------------------
// HMMA fp16 GEMM (R11 exact mainloop). 128x128 CTA tile, 128 threads,
// BK=32, 3-stage cp.async pipeline. 61.4 KB smem -> 3 CTAs/SM.
// ---------------------------------------------------------------------------
#define BKT   32
#define LDS_  40                 // 32 + 8 pad (fp16 elems)
#define TSZ   (128 * LDS_ * 2)   // 10240 B per tile
#define STAGE (2 * TSZ)          // 20480 B (A + B)
#define SMEM_GEMM (3 * STAGE)    // 61440 B

__device__ __forceinline__ void hmma_gemm_body(
    const __half* __restrict__ A, const __half* __restrict__ W,
    const float* __restrict__ bias_tile, float* __restrict__ C,
    int nk, int lda, int ldw, int ldc)
{
    extern __shared__ char smem[];
    const uint32_t smb = smem_u32(smem);

    const int bm = blockIdx.y * 128;
    const int bn = blockIdx.x * 128;
    const int tid = threadIdx.x;                 // 0..127
    const int lane = tid & 31, wid = tid >> 5;   // 4 warps
    const int wm = (wid & 1) * 64;
    const int wn = (wid >> 1) * 64;

    float acc[4][8][4] = {};

    auto issue = [&](int it2) {
        if (it2 < nk) {
            const uint32_t st = smb + (it2 % 3) * STAGE;
            const int cb = it2 * BKT;
#pragma unroll
            for (int i = 0; i < 4; i++) {
                const int idx = tid + i * 128;
                const int row = idx >> 2;           // 0..127
                const int col = (idx & 3) * 8;      // 0,8,16,24
                const uint32_t so = (uint32_t)(row * LDS_ + col) * 2;
                cp_async16(st +       so, A + (size_t)(bm + row) * lda + cb + col);
                cp_async16(st + TSZ + so, W + (size_t)(bn + row) * ldw + cb + col);
            }
        }
        CP_COMMIT();
    };

    issue(0);
    issue(1);

    const int a_row = wm + (lane & 15);
    const int a_kof = (lane >> 4) * 8;
    const int b_row = wn + (lane & 7) + (lane >> 4) * 8;
    const int b_kof = ((lane >> 3) & 1) * 8;

    for (int it = 0; it < nk; ++it) {
        CP_WAIT1();
        __syncthreads();
        issue(it + 2);

        const uint32_t st = smb + (it % 3) * STAGE;
        const uint32_t sA = st;
        const uint32_t sB = st + TSZ;
#pragma unroll
        for (int ks = 0; ks < 2; ++ks) {
            const int k0 = ks * 16;
            uint32_t af[4][4], bf[4][4];
#pragma unroll
            for (int mi = 0; mi < 4; mi++)
                ldmx4(af[mi], sA + (uint32_t)((a_row + mi * 16) * LDS_ + k0 + a_kof) * 2);
#pragma unroll
            for (int g2 = 0; g2 < 4; g2++)
                ldmx4(bf[g2], sB + (uint32_t)((b_row + g2 * 16) * LDS_ + k0 + b_kof) * 2);
#pragma unroll
            for (int mi = 0; mi < 4; mi++)
#pragma unroll
                for (int ni = 0; ni < 8; ni++)
                    mma16816(acc[mi][ni], af[mi],
                             bf[ni >> 1][(ni & 1) * 2], bf[ni >> 1][(ni & 1) * 2 + 1]);
        }
    }

    const int g = lane >> 2, t = lane & 3;
#pragma unroll
    for (int mi = 0; mi < 4; mi++) {
        const int row0 = bm + wm + mi * 16 + g;
#pragma unroll
        for (int ni = 0; ni < 8; ni++) {
            const int colL = wn + ni * 8 + t * 2;
            float b0 = 0.f, b1 = 0.f;
            if (bias_tile) { b0 = bias_tile[colL]; b1 = bias_tile[colL + 1]; }
            float2 v0 = {acc[mi][ni][0] + b0, acc[mi][ni][1] + b1};
            float2 v1 = {acc[mi][ni][2] + b0, acc[mi][ni][3] + b1};
            *reinterpret_cast<float2*>(&C[(size_t)row0 * ldc + bn + colL]) = v0;
            *reinterpret_cast<float2*>(&C[(size_t)(row0 + 8) * ldc + bn + colL]) = v1;
        }
    }
}

__global__ __launch_bounds__(128, 3) void hmma_qkv_kernel(
    const float* __restrict__ Qb, const float* __restrict__ Kb,
    const float* __restrict__ Vb)
{
    const int bn = blockIdx.x * 128;
    const __half* A = (bn < KOFF) ? gb_q : (bn < VOFF) ? gb_k : gb_v;
    const float* bias = (bn < KOFF) ? (Qb + bn)
                      : (bn < VOFF) ? (Kb + bn - KOFF)
                                    : (Vb + bn - VOFF);
    hmma_gemm_body(A, gb_w, bias, g_qkv, KE_P / BKT, KE_P, KE_P, QKVW);
}

__global__ __launch_bounds__(128, 3) void hmma_col_kernel()
{
    const int z = blockIdx.z;            // 56 chunks of 32: 14 per z
    const int cstart = z * 14;
    hmma_gemm_body(gb_at + cstart * BKT, gb_Ck + cstart * BKT, nullptr,
                   g_part + (size_t)z * (B_ * N_ * DM),
                   14, VW, VW, DM);
}

// ---------------------------------------------------------------------------
// fp32 -> fp16 conversions
// ---------------------------------------------------------------------------
__device__ __forceinline__ void cvt_act(
    const float* __restrict__ inrow, __half* __restrict__ outrow, int k, int K)
{
    const float2 x = reinterpret_cast<const float2*>(inrow)[k];
    const __half h0 = __float2half_rn(x.x);
    const __half h1 = __float2half_rn(x.y);
    const __half l0 = __float2half_rn(x.x - __half2float(h0));
    const __half l1 = __float2half_rn(x.y - __half2float(h1));
    __half2 hh; hh.x = h0; hh.y = h1;
    __half2 ll; ll.x = l0; ll.y = l1;
    __half2* orow = reinterpret_cast<__half2*>(outrow);
    orow[k] = hh;
    orow[(K >> 1) + k] = ll;
}
__device__ __forceinline__ void cvt_wt(
    const float* __restrict__ inrow, __half* __restrict__ outrow, int k, int K)
{
    const float2 x = reinterpret_cast<const float2*>(inrow)[k];
    __half2 hh; hh.x = __float2half_rn(x.x); hh.y = __float2half_rn(x.y);
    __half2* orow = reinterpret_cast<__half2*>(outrow);
    orow[k] = hh;
    orow[(K >> 1) + k] = hh;     // duplicate hi
}

__global__ __launch_bounds__(256) void cvt_qkv_kernel(
    const float* __restrict__ q, const float* __restrict__ k,
    const float* __restrict__ v)
{
    const int i = blockIdx.x * 256 + threadIdx.x;
    if (i >= B_ * N_ * DM / 2) return;
    const int which = blockIdx.y;
    const float* in = (which == 0) ? q : (which == 1) ? k : v;
    __half* out = (which == 0) ? gb_q : (which == 1) ? gb_k : gb_v;
    const int r = i / (DM / 2), kk = i % (DM / 2);
    cvt_act(in + (size_t)r * DM, out + (size_t)r * KE_P, kk, DM);
}

#define WPAIRS (QKVW * DM / 2)
#define CPAIRS (DM * VW / 2)
__global__ __launch_bounds__(256) void cvt_wts_kernel(
    const float* __restrict__ Qk, const float* __restrict__ Kk,
    const float* __restrict__ Vk, const float* __restrict__ Ck)
{
    const int i = blockIdx.x * 256 + threadIdx.x;
    if (i < WPAIRS) {
        const int r = i / (DM / 2), kk = i % (DM / 2);
        const float* src = (r < KOFF) ? (Qk + (size_t)r * DM)
                         : (r < VOFF) ? (Kk + (size_t)(r - KOFF) * DM)
                                      : (Vk + (size_t)(r - VOFF) * DM);
        cvt_wt(src, gb_w + (size_t)r * KE_P, kk, DM);
    } else if (i < WPAIRS + CPAIRS) {
        const int j = i - WPAIRS;
        const float2 x = reinterpret_cast<const float2*>(Ck)[j];
        __half2 hh; hh.x = __float2half_rn(x.x); hh.y = __float2half_rn(x.y);
        reinterpret_cast<__half2*>(gb_Ck)[j] = hh;
    }
}

__global__ __launch_bounds__(256) void add_bias_kernel(
    const float* __restrict__ Cb, float* __restrict__ out)
{
    const int i = blockIdx.x * 256 + threadIdx.x;
    const float4 p0 = reinterpret_cast<const float4*>(g_part)[i];
    const float4 p1 = reinterpret_cast<const float4*>(g_part + (size_t)B_ * N_ * DM)[i];
    const float4 p2 = reinterpret_cast<const float4*>(g_part + (size_t)2 * B_ * N_ * DM)[i];
    const float4 p3 = reinterpret_cast<const float4*>(g_part + (size_t)3 * B_ * N_ * DM)[i];
    const float4 bb = reinterpret_cast<const float4*>(Cb)[i % (DM / 4)];
    float4 o = {p0.x + p1.x + p2.x + p3.x + bb.x,
                p0.y + p1.y + p2.y + p3.y + bb.y,
                p0.z + p1.z + p2.z + p3.z + bb.z,
                p0.w + p1.w + p2.w + p3.w + bb.w};
    reinterpret_cast<float4*>(out)[i] = o;
}

// ---------------------------------------------------------------------------
// Fused banded attention, balanced head-groups + fused PS/softmax +
// u-loop apply (each warp reads its 56-row union of V once).
// Grid (32, 7, B), 256 threads.
// ---------------------------------------------------------------------------
#define ATN_KV0  0
#define ATN_KV1  8064
#define ATN_SSC  16128
#define ATN_SKT  17184
#define ATN_SHS  20352
#define SMEM_ATTN ((20352 + 1056) * 4)    // 85632 B -> 2 CTAs/SM

__global__ __launch_bounds__(256) void attn_fused_kernel(
    const float* __restrict__ Kb, const float* __restrict__ Vb,
    const float* __restrict__ Sk, const float* __restrict__ Sb)
{
    extern __shared__ float sm[];
    float* kvb[2] = { sm + ATN_KV0, sm + ATN_KV1 };
    float* ssc = sm + ATN_SSC;
    float* skt = sm + ATN_SKT;
    float* shs = sm + ATN_SHS;

    const int z   = blockIdx.x;
    const int g   = blockIdx.y;
    const int b   = blockIdx.z;
    const int tid = threadIdx.x;
    const int lane = tid & 31;
    const int wrp  = tid >> 5;

    const int s     = c_gs[g];
    const int hbase = c_gh[g];
    const int hcnt  = c_gn[g];

    const int dil = c_dil[s];
    const int pl  = ((KC - 1) * dil) >> 1;
    const int cpr = 32 / dil;
    const int r0  = z / cpr;
    const int c0  = z % cpr;
    const int n0  = r0 + c0 * 32 * dil;
    const int base = n0 - pl;

    auto issue_tile = [&](float* dst, int off, const float* bias_row) {
        for (int i = tid; i < 63 * 32; i += 256) {
            const int u  = i >> 5;
            const int c4 = (i & 31) * 4;
            const int idx = base + u * dil;
            const float* src = (idx >= 0 && idx < N_)
                ? g_qkv + (size_t)(b * N_ + idx) * QKVW + off + c4
                : bias_row + c4;
            cp_async16(smem_u32(dst + u * DH + c4), src);
        }
    };

    issue_tile(kvb[0], KOFF + s * DH, Kb + s * DH);           // K tile
    CP_COMMIT();
    issue_tile(kvb[1], VOFF + hbase * DH, Vb + hbase * DH);   // V(h0)
    CP_COMMIT();

    // preload group Sk transposed: skt[hi][k*33 + j] = Sk[h][j][k]
    for (int hi = 0; hi < hcnt; hi++) {
        const float* skh = Sk + (size_t)(hbase + hi) * KC * KC;
        for (int i = tid; i < KC * KC; i += 256) {
            const int j = i >> 5, k = i & 31;
            skt[hi * 1056 + k * 33 + j] = skh[i];
        }
    }

    CP_WAIT1();          // K tile ready (V0 may still be in flight)
    __syncthreads();

    // ---- scores from kvb[0] ----
#pragma unroll
    for (int ti = 0; ti < 4; ti++) {
        const int t  = wrp + ti * 8;
        const int nt = n0 + t * dil;
        const float4 ql = *reinterpret_cast<const float4*>(
            g_qkv + (size_t)(b * N_ + nt) * QKVW + s * DH + lane * 4);
#pragma unroll
        for (int k = 0; k < KC; k++) {
            const float4 kf = *reinterpret_cast<const float4*>(
                kvb[0] + (t + k) * DH + lane * 4);
            float p = ql.x*kf.x + ql.y*kf.y + ql.z*kf.z + ql.w*kf.w;
            p += __shfl_xor_sync(0xffffffffu, p, 16);
            p += __shfl_xor_sync(0xffffffffu, p, 8);
            p += __shfl_xor_sync(0xffffffffu, p, 4);
            p += __shfl_xor_sync(0xffffffffu, p, 2);
            p += __shfl_xor_sync(0xffffffffu, p, 1);
            if (lane == 0) ssc[t * 33 + k] = p;
        }
    }
    __syncthreads();

    int cur = 1;
    for (int hi = 0; hi < hcnt; hi++) {
        const int h = hbase + hi;
        const float* skh = skt + hi * 1056;
        const float sb = Sb[h * KC + lane];

        // fused Pos_Sampling + softmax: warp handles rows t = wrp*4 + r
#pragma unroll
        for (int r = 0; r < 4; r++) {
            const int t = wrp * 4 + r;
            float acc = sb;
#pragma unroll
            for (int k = 0; k < KC; k++)
                acc += ssc[t * 33 + k] * skh[k * 33 + lane];
            float m = acc;
            m = fmaxf(m, __shfl_xor_sync(0xffffffffu, m, 16));
            m = fmaxf(m, __shfl_xor_sync(0xffffffffu, m, 8));
            m = fmaxf(m, __shfl_xor_sync(0xffffffffu, m, 4));
            m = fmaxf(m, __shfl_xor_sync(0xffffffffu, m, 2));
            m = fmaxf(m, __shfl_xor_sync(0xffffffffu, m, 1));
            const float e = expf(acc - m);
            float ssum = e;
            ssum += __shfl_xor_sync(0xffffffffu, ssum, 16);
            ssum += __shfl_xor_sync(0xffffffffu, ssum, 8);
            ssum += __shfl_xor_sync(0xffffffffu, ssum, 4);
            ssum += __shfl_xor_sync(0xffffffffu, ssum, 2);
            ssum += __shfl_xor_sync(0xffffffffu, ssum, 1);
            shs[t * 33 + lane] = e / ssum;
        }

        CP_WAIT0();          // V(hi) ready
        __syncthreads();     // publishes shs + V tile

        if (hi + 1 < hcnt)
            issue_tile(kvb[cur ^ 1], VOFF + (h + 1) * DH, Vb + (h + 1) * DH);
        CP_COMMIT();

        // ---- apply via u-loop: one pass over the warp's 56-row union ----
        const float* kv = kvb[cur];
        const int dq = lane * 4;
        float4 acc[4];
#pragma unroll
        for (int tt = 0; tt < 4; tt++) acc[tt] = make_float4(0.f, 0.f, 0.f, 0.f);

#pragma unroll 8
        for (int uu = 0; uu < 56; uu++) {
            const int u = wrp + uu;
            const float4 v = *reinterpret_cast<const float4*>(kv + u * DH + dq);
#pragma unroll
            for (int tt = 0; tt < 4; tt++) {
                const int j = uu - tt * 8;           // u - t
                if (j >= 0 && j < 32) {
                    const int t = wrp + tt * 8;
                    const float wv = shs[t * 33 + j];
                    acc[tt].x += wv * v.x; acc[tt].y += wv * v.y;
                    acc[tt].z += wv * v.z; acc[tt].w += wv * v.w;
                }
            }
        }

#pragma unroll
        for (int tt = 0; tt < 4; tt++) {
            const int t  = wrp + tt * 8;
            const int nt = n0 + t * dil;
            __half2 hp0; hp0.x = __float2half_rn(acc[tt].x); hp0.y = __float2half_rn(acc[tt].y);
            __half2 hp1; hp1.x = __float2half_rn(acc[tt].z); hp1.y = __float2half_rn(acc[tt].w);
            uint2 hv;
            hv.x = *reinterpret_cast<uint32_t*>(&hp0);
            hv.y = *reinterpret_cast<uint32_t*>(&hp1);
            *reinterpret_cast<uint2*>(
                gb_at + (size_t)(b * N_ + nt) * VW + h * DH + dq) = hv;
        }
        __syncthreads();
        cur ^= 1;
    }
}

extern "C" void kernel_launch(void* const* d_in, const int* in_sizes, int n_in,
                              void* d_out, int out_size)
{
    const float* query = (const float*)d_in[0];
    const float* key   = (const float*)d_in[1];
    const float* value = (const float*)d_in[2];
    const float* Qk    = (const float*)d_in[3];
    const float* Qb    = (const float*)d_in[4];
    const float* Kk    = (const float*)d_in[5];
    const float* Kb    = (const float*)d_in[6];
    const float* Vk    = (const float*)d_in[7];
    const float* Vb    = (const float*)d_in[8];
    const float* Sk    = (const float*)d_in[9];
    const float* Sb    = (const float*)d_in[10];
    const float* Ck    = (const float*)d_in[11];
    const float* Cb    = (const float*)d_in[12];
    float* out = (float*)d_out;

    cudaFuncSetAttribute(hmma_qkv_kernel,
        cudaFuncAttributeMaxDynamicSharedMemorySize, SMEM_GEMM);
    cudaFuncSetAttribute(hmma_col_kernel,
        cudaFuncAttributeMaxDynamicSharedMemorySize, SMEM_GEMM);
    cudaFuncSetAttribute(attn_fused_kernel,
        cudaFuncAttributeMaxDynamicSharedMemorySize, SMEM_ATTN);

    const int M = B_ * N_;  // 2048

    {   // activations q/k/v [xh|xl] in one launch
        const int pairs = M * DM / 2;
        dim3 grid((pairs + 255) / 256, 3);
        cvt_qkv_kernel<<<grid, 256>>>(query, key, value);
    }
    {   // merged weight conversions
        const int pairs = WPAIRS + CPAIRS;
        cvt_wts_kernel<<<(pairs + 255) / 256, 256>>>(Qk, Kk, Vk, Ck);
    }
    {   // fused Q|K|V projection: grid (24, 16) = 384 CTAs, 3 CTAs/SM
        dim3 grid(QKVW / 128, M / 128);
        hmma_qkv_kernel<<<grid, 128, SMEM_GEMM>>>(Qb, Kb, Vb);
    }
    {   // balanced banded attention: grid (32, 7, B)
        dim3 grid(32, 7, B_);
        attn_fused_kernel<<<grid, 256, SMEM_ATTN>>>(Kb, Vb, Sk, Sb);
    }
    {   // collapse split-K=4 over fp16 gb_at: grid (5, 16, 4)
        dim3 grid(DM / 128, M / 128, ZSPLIT);
        hmma_col_kernel<<<grid, 128, SMEM_GEMM>>>();
    }
    add_bias_kernel<<<(M * DM / 4) / 256, 256>>>(Cb, out);
}